// round 13
// baseline (speedup 1.0000x reference)
#include <cuda_runtime.h>
#include <cuda_fp16.h>
#include <stdint.h>
#include <math.h>

#define NPTS 200000
#define CCH  128
#define EPSV 1e-5f
#define ATILE 65536u            // 256 x 128 halfs, swizzled
#define BTILE 32768u            // 128 x 128 halfs, swizzled
#define BM    256

// ---------------- scratch (device globals; no allocations anywhere) ----------
__device__ float  g_x[NPTS * CCH];           // fp32 pooled sums (encoder)
__device__ float  g_dv[NPTS * 14];           // fp32 dvox (head output)
__device__ __half g_yh[NPTS * CCH];          // fp16 conv output
__device__ __half g_xh[NPTS * CCH];          // fp16 x path (input / residual)
__device__ __half g_ah[NPTS * CCH];          // fp16 mid path
__device__ __half g_wh[4 * 27 * CCH * CCH];  // fp16 conv weights
__device__ __half g_w1h[CCH * 64];           // fp16 head weights
__device__ float  g_cnt[NPTS];
__device__ float  g_stats[256];              // [0..127]=sum [128..255]=sumsq

// ---------------- helpers ----------------
__device__ __forceinline__ unsigned smem_u32(const void* p) {
    return (unsigned)__cvta_generic_to_shared(p);
}
__device__ __forceinline__ unsigned swz(int row, int c16) {
    return (unsigned)(row * 256 + (((c16) ^ (row & 7)) << 4));
}
__device__ __forceinline__ unsigned swz64(int row, int c16) {
    return (unsigned)(row * 128 + (((c16) ^ (row & 7)) << 4));
}
__device__ __forceinline__ void ldsm_x4(uint32_t* r, unsigned addr) {
    asm volatile("ldmatrix.sync.aligned.m8n8.x4.shared.b16 {%0,%1,%2,%3}, [%4];\n"
                 : "=r"(r[0]), "=r"(r[1]), "=r"(r[2]), "=r"(r[3]) : "r"(addr));
}
__device__ __forceinline__ void ldsm_x4_t(uint32_t* r, unsigned addr) {
    asm volatile("ldmatrix.sync.aligned.m8n8.x4.trans.shared.b16 {%0,%1,%2,%3}, [%4];\n"
                 : "=r"(r[0]), "=r"(r[1]), "=r"(r[2]), "=r"(r[3]) : "r"(addr));
}
__device__ __forceinline__ void mma_f16(float* c, const uint32_t* a, uint32_t b0, uint32_t b1) {
    asm volatile("mma.sync.aligned.m16n8k16.row.col.f32.f16.f16.f32 "
                 "{%0,%1,%2,%3}, {%4,%5,%6,%7}, {%8,%9}, {%0,%1,%2,%3};\n"
                 : "+f"(c[0]), "+f"(c[1]), "+f"(c[2]), "+f"(c[3])
                 : "r"(a[0]), "r"(a[1]), "r"(a[2]), "r"(a[3]), "r"(b0), "r"(b1));
}
__device__ __forceinline__ void cp16(unsigned dst, const void* src) {
    asm volatile("cp.async.cg.shared.global [%0], [%1], 16;\n" :: "r"(dst), "l"(src));
}
__device__ __forceinline__ void cp16z(unsigned dst, const void* src, unsigned ssz) {
    asm volatile("cp.async.cg.shared.global [%0], [%1], 16, %2;\n"
                 :: "r"(dst), "l"(src), "r"(ssz));
}

// ---------------- weight fp32 -> fp16 ----------------
__global__ void convert_w_kernel(const float* __restrict__ w, __half* __restrict__ wh, int n) {
    for (int i = blockIdx.x * blockDim.x + threadIdx.x; i < n; i += gridDim.x * blockDim.x)
        wh[i] = __float2half(w[i]);
}

// ---------------- encoder: warp-per-point Linear+LN+ReLU + segment-sum --------
__global__ __launch_bounds__(256)
void encode_pool_kernel(const float* __restrict__ gp,
                        const float* __restrict__ w_enc,
                        const float* __restrict__ b_enc,
                        const float* __restrict__ ln_g,
                        const float* __restrict__ ln_b,
                        const int*   __restrict__ inv_idx,
                        float* __restrict__ xsum,
                        float* __restrict__ cnt,
                        int Np) {
    const int lane = threadIdx.x & 31;
    const int gw = (blockIdx.x * blockDim.x + threadIdx.x) >> 5;
    const int nw = (gridDim.x * blockDim.x) >> 5;
    const int c0 = lane * 4;

    float wreg[14][4];
#pragma unroll
    for (int k = 0; k < 14; ++k) {
        float4 t = *(const float4*)(w_enc + k * CCH + c0);
        wreg[k][0] = t.x; wreg[k][1] = t.y; wreg[k][2] = t.z; wreg[k][3] = t.w;
    }
    float4 be = *(const float4*)(b_enc + c0);
    float4 lg = *(const float4*)(ln_g + c0);
    float4 lb = *(const float4*)(ln_b + c0);

    for (int i = gw; i < Np; i += nw) {
        float gv = (lane < 14) ? gp[(size_t)i * 14 + lane] : 0.f;
        float f0 = be.x, f1 = be.y, f2 = be.z, f3 = be.w;
#pragma unroll
        for (int k = 0; k < 14; ++k) {
            float s = __shfl_sync(0xffffffffu, gv, k);
            f0 += s * wreg[k][0]; f1 += s * wreg[k][1];
            f2 += s * wreg[k][2]; f3 += s * wreg[k][3];
        }
        float s1 = f0 + f1 + f2 + f3;
        float s2 = f0 * f0 + f1 * f1 + f2 * f2 + f3 * f3;
#pragma unroll
        for (int off = 16; off > 0; off >>= 1) {
            s1 += __shfl_xor_sync(0xffffffffu, s1, off);
            s2 += __shfl_xor_sync(0xffffffffu, s2, off);
        }
        float mu  = s1 * (1.f / 128.f);
        float inv = rsqrtf(s2 * (1.f / 128.f) - mu * mu + EPSV);
        int vox = inv_idx[i];
        float* dst = xsum + (size_t)vox * CCH + c0;
        atomicAdd(dst + 0, fmaxf((f0 - mu) * inv * lg.x + lb.x, 0.f));
        atomicAdd(dst + 1, fmaxf((f1 - mu) * inv * lg.y + lb.y, 0.f));
        atomicAdd(dst + 2, fmaxf((f2 - mu) * inv * lg.z + lb.z, 0.f));
        atomicAdd(dst + 3, fmaxf((f3 - mu) * inv * lg.w + lb.w, 0.f));
        if (lane == 0) atomicAdd(&cnt[vox], 1.f);
    }
}

// ---------------- pooled sums / counts -> fp16 only ---------------------------
__global__ void pool_div_kernel(const float* __restrict__ x, const float* __restrict__ cnt,
                                __half* __restrict__ xh, int M) {
    int total = M * CCH;
    for (int i = blockIdx.x * blockDim.x + threadIdx.x; i < total; i += gridDim.x * blockDim.x)
        xh[i] = __float2half(x[i] / cnt[i >> 7]);
}

// ---------------- submanifold conv, fp16 mma.sync, cp.async double-buffered ---
// 256x128 tile / 512 threads (16 warps, 8x2). Per-offset 16-bit fragment
// activity mask: inactive 16-row fragments skip BOTH staging and mma (exact).
// BN sum/sumsq accumulated in fp32 from registers (pre-quantization);
// y stored fp16 (half2 packed) to halve output DRAM traffic.
__global__ __launch_bounds__(512, 1)
void subm_conv_mma_kernel(const __half* __restrict__ xin,
                          const __half* __restrict__ W,   // 27 x 128 x 128 fp16
                          const int*   __restrict__ nbr_idx,
                          const float* __restrict__ nbr_mask,
                          __half* __restrict__ y,          // fp16 out
                          float* __restrict__ gstats,
                          int M) {
    extern __shared__ __align__(16) char smem_raw[];
    int* sidx = (int*)(smem_raw + 2 * ATILE + 2 * BTILE);   // 27 x 256
    __shared__ unsigned s_fmask[27];
    __shared__ int   s_sal[27], s_nact;
    __shared__ float sstat[CCH], ssq[CCH];

    const int tid  = threadIdx.x;
    const int warp = tid >> 5, lane = tid & 31;
    const int wm = warp >> 1;
    const int wn = warp & 1;
    const int v0 = blockIdx.x * BM;

    for (int j = tid; j < 27 * BM; j += 512) {
        int r = j / 27, o = j - r * 27;
        int v = v0 + r;
        int id = -1;
        if (v < M && nbr_mask[(size_t)v0 * 27 + j] != 0.f)
            id = nbr_idx[(size_t)v0 * 27 + j];
        sidx[o * BM + r] = id;
    }
    if (tid < 27) s_fmask[tid] = 0u;
    if (tid < CCH) { sstat[tid] = 0.f; ssq[tid] = 0.f; }
    __syncthreads();
    if (tid < 432) {
        int o = tid >> 4, f = tid & 15;
        const int* p = sidx + o * BM + f * 16;
        int any = 0;
#pragma unroll
        for (int i = 0; i < 16; ++i) any |= (p[i] >= 0);
        if (any) atomicOr(&s_fmask[o], 1u << f);
    }
    __syncthreads();
    if (tid == 0) {
        int n = 0;
        for (int o = 0; o < 27; ++o) if (s_fmask[o]) s_sal[n++] = o;
        s_nact = n;
    }
    __syncthreads();
    const int nact = s_nact;

    const unsigned sAu = smem_u32(smem_raw);
    const unsigned sBu = sAu + 2 * ATILE;
    const int arow = tid >> 1;
    const int ac0  = (tid & 1) * 8;
    const int afrag = arow >> 4;
    const int brow = tid >> 2;
    const int bc0  = (tid & 3) * 4;

    float acc[2][8][4];
#pragma unroll
    for (int mi = 0; mi < 2; ++mi)
#pragma unroll
        for (int ni = 0; ni < 8; ++ni)
#pragma unroll
            for (int q = 0; q < 4; ++q) acc[mi][ni][q] = 0.f;

    {   // stage offset 0 into buffer 0
        int o = s_sal[0];
        if ((s_fmask[o] >> afrag) & 1u) {
            int id = sidx[o * BM + arow];
            unsigned ssz = (id >= 0) ? 16u : 0u;
            const __half* srcA = xin + (size_t)(id >= 0 ? id : 0) * CCH + ac0 * 8;
#pragma unroll
            for (int q = 0; q < 8; ++q)
                cp16z(sAu + swz(arow, ac0 + q), srcA + q * 8, ssz);
        }
        const __half* srcB = W + (size_t)o * CCH * CCH + brow * CCH + bc0 * 8;
#pragma unroll
        for (int q = 0; q < 4; ++q)
            cp16 (sBu + swz(brow, bc0 + q), srcB + q * 8);
        asm volatile("cp.async.commit_group;\n" ::: "memory");
    }

    for (int t = 0; t < nact; ++t) {
        const int b = t & 1;
        const unsigned fmask = s_fmask[s_sal[t]];
        const bool act0 = (fmask >> (2 * wm)) & 1u;
        const bool act1 = (fmask >> (2 * wm + 1)) & 1u;

        asm volatile("cp.async.wait_group 0;\n" ::: "memory");
        __syncthreads();
        if (t + 1 < nact) {
            int o = s_sal[t + 1];
            unsigned dA = sAu + (unsigned)((b ^ 1) * ATILE);
            unsigned dB = sBu + (unsigned)((b ^ 1) * BTILE);
            if ((s_fmask[o] >> afrag) & 1u) {
                int id = sidx[o * BM + arow];
                unsigned ssz = (id >= 0) ? 16u : 0u;
                const __half* srcA = xin + (size_t)(id >= 0 ? id : 0) * CCH + ac0 * 8;
#pragma unroll
                for (int q = 0; q < 8; ++q)
                    cp16z(dA + swz(arow, ac0 + q), srcA + q * 8, ssz);
            }
            const __half* srcB = W + (size_t)o * CCH * CCH + brow * CCH + bc0 * 8;
#pragma unroll
            for (int q = 0; q < 4; ++q)
                cp16 (dB + swz(brow, bc0 + q), srcB + q * 8);
            asm volatile("cp.async.commit_group;\n" ::: "memory");
        }

        if (act0 | act1) {
            const unsigned Ab = sAu + (unsigned)(b * ATILE);
            const unsigned Bb = sBu + (unsigned)(b * BTILE);
#pragma unroll
            for (int kc = 0; kc < 8; ++kc) {
                uint32_t a[2][4];
                if (act0) {
                    int row = wm * 32 + (lane & 15);
                    ldsm_x4(a[0], Ab + swz(row, kc * 2 + (lane >> 4)));
                }
                if (act1) {
                    int row = wm * 32 + 16 + (lane & 15);
                    ldsm_x4(a[1], Ab + swz(row, kc * 2 + (lane >> 4)));
                }
#pragma unroll
                for (int nb = 0; nb < 4; ++nb) {
                    uint32_t bb[4];
                    int row = kc * 16 + (lane & 15);
                    ldsm_x4_t(bb, Bb + swz(row, wn * 8 + nb * 2 + (lane >> 4)));
                    if (act0) {
                        mma_f16(acc[0][nb * 2 + 0], a[0], bb[0], bb[1]);
                        mma_f16(acc[0][nb * 2 + 1], a[0], bb[2], bb[3]);
                    }
                    if (act1) {
                        mma_f16(acc[1][nb * 2 + 0], a[1], bb[0], bb[1]);
                        mma_f16(acc[1][nb * 2 + 1], a[1], bb[2], bb[3]);
                    }
                }
            }
        }
        __syncthreads();
    }

    // ---- epilogue: fp16 packed y stores + fp32 BN partials -------------------
    const int rbase = v0 + wm * 32 + (lane >> 2);
    const int cbase = wn * 64 + (lane & 3) * 2;
    __half2* y2 = (__half2*)y;
#pragma unroll
    for (int mi = 0; mi < 2; ++mi) {
#pragma unroll
        for (int ni = 0; ni < 8; ++ni) {
            int col = cbase + ni * 8;
            int r0 = rbase + mi * 16;
            if (r0 < M)
                y2[((size_t)r0 * CCH + col) >> 1] =
                    __floats2half2_rn(acc[mi][ni][0], acc[mi][ni][1]);
            int r1 = r0 + 8;
            if (r1 < M)
                y2[((size_t)r1 * CCH + col) >> 1] =
                    __floats2half2_rn(acc[mi][ni][2], acc[mi][ni][3]);
        }
    }
#pragma unroll
    for (int ni = 0; ni < 8; ++ni) {
#pragma unroll
        for (int tt = 0; tt < 2; ++tt) {
            float a0 = acc[0][ni][tt],     a1 = acc[0][ni][2 + tt];
            float a2 = acc[1][ni][tt],     a3 = acc[1][ni][2 + tt];
            float s = a0 + a1 + a2 + a3;
            float q = a0 * a0 + a1 * a1 + a2 * a2 + a3 * a3;
#pragma unroll
            for (int off = 4; off <= 16; off <<= 1) {
                s += __shfl_xor_sync(0xffffffffu, s, off);
                q += __shfl_xor_sync(0xffffffffu, q, off);
            }
            if ((lane >> 2) == 0) {
                int c = cbase + ni * 8 + tt;
                atomicAdd(&sstat[c], s);
                atomicAdd(&ssq[c], q);
            }
        }
    }
    __syncthreads();
    if (tid < CCH) {
        atomicAdd(&gstats[tid],       sstat[tid]);
        atomicAdd(&gstats[CCH + tid], ssq[tid]);
    }
}

// ---------------- BN apply: hoisted scale/bias, fp16 in/out -------------------
__global__ __launch_bounds__(256)
void bn_apply_kernel(const __half* __restrict__ y,     // fp16 conv output
                     const float* __restrict__ g,
                     const float* __restrict__ b,
                     const float* __restrict__ stats,
                     const __half* __restrict__ residual,   // nullable (fp16)
                     __half* __restrict__ out_h16,
                     int M) {
    __shared__ float sc[CCH], sb[CCH];
    float invM = 1.f / (float)M;
    if (threadIdx.x < CCH) {
        int c = threadIdx.x;
        float m   = stats[c] * invM;
        float var = stats[128 + c] * invM - m * m;
        float s = rsqrtf(var + EPSV) * g[c];
        sc[c] = s;
        sb[c] = b[c] - m * s;
    }
    __syncthreads();

    int total4 = M * 32;   // groups of 4 channels
    for (int i = blockIdx.x * blockDim.x + threadIdx.x; i < total4; i += gridDim.x * blockDim.x) {
        int c0 = (i & 31) * 4;
        float2 y01 = __half22float2(((const __half2*)y)[2 * i]);
        float2 y23 = __half22float2(((const __half2*)y)[2 * i + 1]);
        float v0 = y01.x * sc[c0]     + sb[c0];
        float v1 = y01.y * sc[c0 + 1] + sb[c0 + 1];
        float v2 = y23.x * sc[c0 + 2] + sb[c0 + 2];
        float v3 = y23.y * sc[c0 + 3] + sb[c0 + 3];
        if (residual) {
            float2 f01 = __half22float2(((const __half2*)residual)[2 * i]);
            float2 f23 = __half22float2(((const __half2*)residual)[2 * i + 1]);
            v0 += f01.x; v1 += f01.y; v2 += f23.x; v3 += f23.y;
        }
        v0 = fmaxf(v0, 0.f); v1 = fmaxf(v1, 0.f);
        v2 = fmaxf(v2, 0.f); v3 = fmaxf(v3, 0.f);
        ((__half2*)out_h16)[2 * i]     = __floats2half2_rn(v0, v1);
        ((__half2*)out_h16)[2 * i + 1] = __floats2half2_rn(v2, v3);
    }
}

// ---------------- head on voxels: dvox = relu(x@w1+b1)@w2 + b2 ----------------
__global__ __launch_bounds__(256)
void head_vox_kernel(const __half* __restrict__ xh,
                     const __half* __restrict__ w1h,
                     const float* __restrict__ b1,
                     const float* __restrict__ w2,
                     const float* __restrict__ b2,
                     float* __restrict__ dvox,
                     int M) {
    extern __shared__ __align__(16) char smem_raw[];
    float* hs = (float*)(smem_raw + 49152);
    __shared__ float b1s[64], b2s[14], w2s[64 * 14];

    const int tid  = threadIdx.x;
    const int warp = tid >> 5, lane = tid & 31;
    const int v0 = blockIdx.x * 128;

    const unsigned sAu = smem_u32(smem_raw);
    const unsigned sBu = sAu + 32768u;

    {
        int row = tid >> 1, c0 = (tid & 1) * 8;
        unsigned ssz = (v0 + row < M) ? 16u : 0u;
        const __half* srcA = xh + (size_t)(v0 + row < M ? v0 + row : 0) * CCH + c0 * 8;
#pragma unroll
        for (int q = 0; q < 8; ++q)
            cp16z(sAu + swz(row, c0 + q), srcA + q * 8, ssz);
    }
    for (int j = tid; j < 1024; j += 256) {
        int row = j >> 3, c = j & 7;
        cp16(sBu + swz64(row, c), w1h + row * 64 + c * 8);
    }
    asm volatile("cp.async.commit_group;\n" ::: "memory");
    if (tid < 64) b1s[tid] = b1[tid];
    if (tid < 14) b2s[tid] = b2[tid];
    for (int j = tid; j < 64 * 14; j += 256) w2s[j] = w2[j];
    asm volatile("cp.async.wait_group 0;\n" ::: "memory");
    __syncthreads();

    float acc[8][4];
#pragma unroll
    for (int ni = 0; ni < 8; ++ni)
#pragma unroll
        for (int q = 0; q < 4; ++q) acc[ni][q] = 0.f;
#pragma unroll
    for (int kc = 0; kc < 8; ++kc) {
        uint32_t a[4];
        ldsm_x4(a, sAu + swz(warp * 16 + (lane & 15), kc * 2 + (lane >> 4)));
#pragma unroll
        for (int nb = 0; nb < 4; ++nb) {
            uint32_t bb[4];
            ldsm_x4_t(bb, sBu + swz64(kc * 16 + (lane & 15), nb * 2 + (lane >> 4)));
            mma_f16(acc[nb * 2 + 0], a, bb[0], bb[1]);
            mma_f16(acc[nb * 2 + 1], a, bb[2], bb[3]);
        }
    }
    {
        int r0 = warp * 16 + (lane >> 2);
        int c0 = (lane & 3) * 2;
#pragma unroll
        for (int ni = 0; ni < 8; ++ni) {
            int c = c0 + ni * 8;
            hs[r0 * 65 + c]           = fmaxf(acc[ni][0] + b1s[c], 0.f);
            hs[r0 * 65 + c + 1]       = fmaxf(acc[ni][1] + b1s[c + 1], 0.f);
            hs[(r0 + 8) * 65 + c]     = fmaxf(acc[ni][2] + b1s[c], 0.f);
            hs[(r0 + 8) * 65 + c + 1] = fmaxf(acc[ni][3] + b1s[c + 1], 0.f);
        }
    }
    __syncthreads();

    {
        int r = tid >> 1;
        int cb = (tid & 1) * 7;
        if (v0 + r < M) {
            float d[7];
#pragma unroll
            for (int c = 0; c < 7; ++c) d[c] = b2s[cb + c];
#pragma unroll 8
            for (int k = 0; k < 64; ++k) {
                float hv = hs[r * 65 + k];
#pragma unroll
                for (int c = 0; c < 7; ++c) d[c] += hv * w2s[k * 14 + cb + c];
            }
            float* dst = dvox + (size_t)(v0 + r) * 14 + cb;
#pragma unroll
            for (int c = 0; c < 7; ++c) dst[c] = d[c];
        }
    }
}

// ---------------- scatter: out = gp + dvox[inv_idx], thread-per-point ---------
__global__ void scatter_out_kernel(const float* __restrict__ gp,
                                   const float* __restrict__ dvox,
                                   const int*   __restrict__ inv_idx,
                                   float* __restrict__ out, int Np) {
    for (int i = blockIdx.x * blockDim.x + threadIdx.x; i < Np; i += gridDim.x * blockDim.x) {
        const float* dr = dvox + (size_t)inv_idx[i] * 14;
        const float* gr = gp + (size_t)i * 14;
        float* orow = out + (size_t)i * 14;
#pragma unroll
        for (int j = 0; j < 14; ++j) orow[j] = gr[j] + dr[j];
    }
}

// ---------------- launch -------------------------------------------------------
extern "C" void kernel_launch(void* const* d_in, const int* in_sizes, int n_in,
                              void* d_out, int out_size) {
    const float* gp       = (const float*)d_in[0];
    const float* w_enc    = (const float*)d_in[1];
    const float* b_enc    = (const float*)d_in[2];
    const float* ln_g     = (const float*)d_in[3];
    const float* ln_b     = (const float*)d_in[4];
    const float* conv_w   = (const float*)d_in[5];
    const float* bn_g     = (const float*)d_in[6];
    const float* bn_b     = (const float*)d_in[7];
    const float* w1       = (const float*)d_in[8];
    const float* b1       = (const float*)d_in[9];
    const float* w2       = (const float*)d_in[10];
    const float* b2       = (const float*)d_in[11];
    const float* nbr_mask = (const float*)d_in[12];
    const int*   inv_idx  = (const int*)d_in[13];
    const int*   nbr_idx  = (const int*)d_in[14];
    float* out = (float*)d_out;

    const int Np = in_sizes[0] / 14;
    const int M  = in_sizes[12] / 27;

    float *px, *pdv, *pcnt, *pstats;
    __half *pyh, *pxh, *pah, *pwh, *pw1h;
    cudaGetSymbolAddress((void**)&px,     g_x);
    cudaGetSymbolAddress((void**)&pdv,    g_dv);
    cudaGetSymbolAddress((void**)&pyh,    g_yh);
    cudaGetSymbolAddress((void**)&pxh,    g_xh);
    cudaGetSymbolAddress((void**)&pah,    g_ah);
    cudaGetSymbolAddress((void**)&pwh,    g_wh);
    cudaGetSymbolAddress((void**)&pw1h,   g_w1h);
    cudaGetSymbolAddress((void**)&pcnt,   g_cnt);
    cudaGetSymbolAddress((void**)&pstats, g_stats);

    const int CONV_SMEM = 2 * ATILE + 2 * BTILE + 27 * BM * 4;  // 224256
    cudaFuncSetAttribute(subm_conv_mma_kernel,
                         cudaFuncAttributeMaxDynamicSharedMemorySize, CONV_SMEM);
    const int HEAD_SMEM = 49152 + 128 * 65 * 4;                 // 82432
    cudaFuncSetAttribute(head_vox_kernel,
                         cudaFuncAttributeMaxDynamicSharedMemorySize, HEAD_SMEM);

    convert_w_kernel<<<1024, 256>>>(conv_w, pwh, 4 * 27 * CCH * CCH);
    convert_w_kernel<<<8, 256>>>(w1, pw1h, CCH * 64);
    cudaMemsetAsync(px, 0, (size_t)M * CCH * sizeof(float));
    cudaMemsetAsync(pcnt, 0, (size_t)M * sizeof(float));
    encode_pool_kernel<<<512, 256>>>(gp, w_enc, b_enc, ln_g, ln_b, inv_idx, px, pcnt, Np);
    pool_div_kernel<<<2048, 256>>>(px, pcnt, pxh, M);

    const int tiles = (M + BM - 1) / BM;
    for (int blk = 0; blk < 2; ++blk) {
        const int l0 = 2 * blk, l1 = 2 * blk + 1;
        // conv1 (fused BN stats, fp16 y) -> BN apply -> ReLU (fp16 out)
        cudaMemsetAsync(pstats, 0, 256 * sizeof(float));
        subm_conv_mma_kernel<<<tiles, 512, CONV_SMEM>>>(
            pxh, pwh + (size_t)l0 * 27 * CCH * CCH, nbr_idx, nbr_mask, pyh, pstats, M);
        bn_apply_kernel<<<2048, 256>>>(pyh, bn_g + l0 * CCH, bn_b + l0 * CCH, pstats,
                                       (const __half*)0, pah, M);
        // conv2 (fused BN stats, fp16 y) -> BN apply + fp16 residual (in-place xh)
        cudaMemsetAsync(pstats, 0, 256 * sizeof(float));
        subm_conv_mma_kernel<<<tiles, 512, CONV_SMEM>>>(
            pah, pwh + (size_t)l1 * 27 * CCH * CCH, nbr_idx, nbr_mask, pyh, pstats, M);
        bn_apply_kernel<<<2048, 256>>>(pyh, bn_g + l1 * CCH, bn_b + l1 * CCH, pstats,
                                       pxh, pxh, M);
    }

    head_vox_kernel<<<(M + 127) / 128, 256, HEAD_SMEM>>>(pxh, pw1h, b1, w2, b2, pdv, M);
    scatter_out_kernel<<<1024, 256>>>(gp, pdv, inv_idx, out, Np);
}

// round 14
// speedup vs baseline: 1.5136x; 1.5136x over previous
#include <cuda_runtime.h>
#include <cuda_fp16.h>
#include <stdint.h>
#include <math.h>

#define NPTS 200000
#define CCH  128
#define EPSV 1e-5f
#define ATILE 65536u            // 256 x 128 halfs, swizzled
#define BTILE 32768u            // 128 x 128 halfs, swizzled
#define BM    256
#define YPITCH 136              // halfs per row in epilogue staging (272B, conflict-free)

// ---------------- scratch (device globals; no allocations anywhere) ----------
__device__ float  g_x[NPTS * CCH];           // fp32 pooled sums (encoder)
__device__ float  g_dv[NPTS * 14];           // fp32 dvox (head output)
__device__ __half g_yh[NPTS * CCH];          // fp16 conv output
__device__ __half g_xh[NPTS * CCH];          // fp16 x path (input / residual)
__device__ __half g_ah[NPTS * CCH];          // fp16 mid path
__device__ __half g_wh[4 * 27 * CCH * CCH];  // fp16 conv weights
__device__ __half g_w1h[CCH * 64];           // fp16 head weights
__device__ float  g_cnt[NPTS];
__device__ float  g_stats[256];              // [0..127]=sum [128..255]=sumsq

// ---------------- helpers ----------------
__device__ __forceinline__ unsigned smem_u32(const void* p) {
    return (unsigned)__cvta_generic_to_shared(p);
}
__device__ __forceinline__ unsigned swz(int row, int c16) {
    return (unsigned)(row * 256 + (((c16) ^ (row & 7)) << 4));
}
__device__ __forceinline__ unsigned swz64(int row, int c16) {
    return (unsigned)(row * 128 + (((c16) ^ (row & 7)) << 4));
}
__device__ __forceinline__ void ldsm_x4(uint32_t* r, unsigned addr) {
    asm volatile("ldmatrix.sync.aligned.m8n8.x4.shared.b16 {%0,%1,%2,%3}, [%4];\n"
                 : "=r"(r[0]), "=r"(r[1]), "=r"(r[2]), "=r"(r[3]) : "r"(addr));
}
__device__ __forceinline__ void ldsm_x4_t(uint32_t* r, unsigned addr) {
    asm volatile("ldmatrix.sync.aligned.m8n8.x4.trans.shared.b16 {%0,%1,%2,%3}, [%4];\n"
                 : "=r"(r[0]), "=r"(r[1]), "=r"(r[2]), "=r"(r[3]) : "r"(addr));
}
__device__ __forceinline__ void mma_f16(float* c, const uint32_t* a, uint32_t b0, uint32_t b1) {
    asm volatile("mma.sync.aligned.m16n8k16.row.col.f32.f16.f16.f32 "
                 "{%0,%1,%2,%3}, {%4,%5,%6,%7}, {%8,%9}, {%0,%1,%2,%3};\n"
                 : "+f"(c[0]), "+f"(c[1]), "+f"(c[2]), "+f"(c[3])
                 : "r"(a[0]), "r"(a[1]), "r"(a[2]), "r"(a[3]), "r"(b0), "r"(b1));
}
__device__ __forceinline__ void cp16(unsigned dst, const void* src) {
    asm volatile("cp.async.cg.shared.global [%0], [%1], 16;\n" :: "r"(dst), "l"(src));
}
__device__ __forceinline__ void cp16z(unsigned dst, const void* src, unsigned ssz) {
    asm volatile("cp.async.cg.shared.global [%0], [%1], 16, %2;\n"
                 :: "r"(dst), "l"(src), "r"(ssz));
}

// ---------------- weight fp32 -> fp16 ----------------
__global__ void convert_w_kernel(const float* __restrict__ w, __half* __restrict__ wh, int n) {
    for (int i = blockIdx.x * blockDim.x + threadIdx.x; i < n; i += gridDim.x * blockDim.x)
        wh[i] = __float2half(w[i]);
}

// ---------------- encoder: warp-per-point Linear+LN+ReLU + segment-sum --------
__global__ __launch_bounds__(256)
void encode_pool_kernel(const float* __restrict__ gp,
                        const float* __restrict__ w_enc,
                        const float* __restrict__ b_enc,
                        const float* __restrict__ ln_g,
                        const float* __restrict__ ln_b,
                        const int*   __restrict__ inv_idx,
                        float* __restrict__ xsum,
                        float* __restrict__ cnt,
                        int Np) {
    const int lane = threadIdx.x & 31;
    const int gw = (blockIdx.x * blockDim.x + threadIdx.x) >> 5;
    const int nw = (gridDim.x * blockDim.x) >> 5;
    const int c0 = lane * 4;

    float wreg[14][4];
#pragma unroll
    for (int k = 0; k < 14; ++k) {
        float4 t = *(const float4*)(w_enc + k * CCH + c0);
        wreg[k][0] = t.x; wreg[k][1] = t.y; wreg[k][2] = t.z; wreg[k][3] = t.w;
    }
    float4 be = *(const float4*)(b_enc + c0);
    float4 lg = *(const float4*)(ln_g + c0);
    float4 lb = *(const float4*)(ln_b + c0);

    for (int i = gw; i < Np; i += nw) {
        float gv = (lane < 14) ? gp[(size_t)i * 14 + lane] : 0.f;
        float f0 = be.x, f1 = be.y, f2 = be.z, f3 = be.w;
#pragma unroll
        for (int k = 0; k < 14; ++k) {
            float s = __shfl_sync(0xffffffffu, gv, k);
            f0 += s * wreg[k][0]; f1 += s * wreg[k][1];
            f2 += s * wreg[k][2]; f3 += s * wreg[k][3];
        }
        float s1 = f0 + f1 + f2 + f3;
        float s2 = f0 * f0 + f1 * f1 + f2 * f2 + f3 * f3;
#pragma unroll
        for (int off = 16; off > 0; off >>= 1) {
            s1 += __shfl_xor_sync(0xffffffffu, s1, off);
            s2 += __shfl_xor_sync(0xffffffffu, s2, off);
        }
        float mu  = s1 * (1.f / 128.f);
        float inv = rsqrtf(s2 * (1.f / 128.f) - mu * mu + EPSV);
        int vox = inv_idx[i];
        float* dst = xsum + (size_t)vox * CCH + c0;
        atomicAdd(dst + 0, fmaxf((f0 - mu) * inv * lg.x + lb.x, 0.f));
        atomicAdd(dst + 1, fmaxf((f1 - mu) * inv * lg.y + lb.y, 0.f));
        atomicAdd(dst + 2, fmaxf((f2 - mu) * inv * lg.z + lb.z, 0.f));
        atomicAdd(dst + 3, fmaxf((f3 - mu) * inv * lg.w + lb.w, 0.f));
        if (lane == 0) atomicAdd(&cnt[vox], 1.f);
    }
}

// ---------------- pooled sums / counts -> fp16 only ---------------------------
__global__ void pool_div_kernel(const float* __restrict__ x, const float* __restrict__ cnt,
                                __half* __restrict__ xh, int M) {
    int total = M * CCH;
    for (int i = blockIdx.x * blockDim.x + threadIdx.x; i < total; i += gridDim.x * blockDim.x)
        xh[i] = __float2half(x[i] / cnt[i >> 7]);
}

// ---------------- submanifold conv, fp16 mma.sync, cp.async double-buffered ---
// 256x128 tile / 512 threads (16 warps, 8x2). Per-offset fragment-activity skip
// (exact). BN sum/sumsq accumulated fp32 from registers (pre-quantization).
// y stored fp16 via smem staging -> fully-coalesced 16B stores (full sectors).
__global__ __launch_bounds__(512, 1)
void subm_conv_mma_kernel(const __half* __restrict__ xin,
                          const __half* __restrict__ W,   // 27 x 128 x 128 fp16
                          const int*   __restrict__ nbr_idx,
                          const float* __restrict__ nbr_mask,
                          __half* __restrict__ y,          // fp16 out
                          float* __restrict__ gstats,
                          int M) {
    extern __shared__ __align__(16) char smem_raw[];
    int* sidx = (int*)(smem_raw + 2 * ATILE + 2 * BTILE);   // 27 x 256
    __shared__ unsigned s_fmask[27];
    __shared__ int   s_sal[27], s_nact;
    __shared__ float sstat[CCH], ssq[CCH];

    const int tid  = threadIdx.x;
    const int warp = tid >> 5, lane = tid & 31;
    const int wm = warp >> 1;
    const int wn = warp & 1;
    const int v0 = blockIdx.x * BM;

    for (int j = tid; j < 27 * BM; j += 512) {
        int r = j / 27, o = j - r * 27;
        int v = v0 + r;
        int id = -1;
        if (v < M && nbr_mask[(size_t)v0 * 27 + j] != 0.f)
            id = nbr_idx[(size_t)v0 * 27 + j];
        sidx[o * BM + r] = id;
    }
    if (tid < 27) s_fmask[tid] = 0u;
    if (tid < CCH) { sstat[tid] = 0.f; ssq[tid] = 0.f; }
    __syncthreads();
    if (tid < 432) {
        int o = tid >> 4, f = tid & 15;
        const int* p = sidx + o * BM + f * 16;
        int any = 0;
#pragma unroll
        for (int i = 0; i < 16; ++i) any |= (p[i] >= 0);
        if (any) atomicOr(&s_fmask[o], 1u << f);
    }
    __syncthreads();
    if (tid == 0) {
        int n = 0;
        for (int o = 0; o < 27; ++o) if (s_fmask[o]) s_sal[n++] = o;
        s_nact = n;
    }
    __syncthreads();
    const int nact = s_nact;

    const unsigned sAu = smem_u32(smem_raw);
    const unsigned sBu = sAu + 2 * ATILE;
    const int arow = tid >> 1;
    const int ac0  = (tid & 1) * 8;
    const int afrag = arow >> 4;
    const int brow = tid >> 2;
    const int bc0  = (tid & 3) * 4;

    float acc[2][8][4];
#pragma unroll
    for (int mi = 0; mi < 2; ++mi)
#pragma unroll
        for (int ni = 0; ni < 8; ++ni)
#pragma unroll
            for (int q = 0; q < 4; ++q) acc[mi][ni][q] = 0.f;

    {   // stage offset 0 into buffer 0
        int o = s_sal[0];
        if ((s_fmask[o] >> afrag) & 1u) {
            int id = sidx[o * BM + arow];
            unsigned ssz = (id >= 0) ? 16u : 0u;
            const __half* srcA = xin + (size_t)(id >= 0 ? id : 0) * CCH + ac0 * 8;
#pragma unroll
            for (int q = 0; q < 8; ++q)
                cp16z(sAu + swz(arow, ac0 + q), srcA + q * 8, ssz);
        }
        const __half* srcB = W + (size_t)o * CCH * CCH + brow * CCH + bc0 * 8;
#pragma unroll
        for (int q = 0; q < 4; ++q)
            cp16 (sBu + swz(brow, bc0 + q), srcB + q * 8);
        asm volatile("cp.async.commit_group;\n" ::: "memory");
    }

    for (int t = 0; t < nact; ++t) {
        const int b = t & 1;
        const unsigned fmask = s_fmask[s_sal[t]];
        const bool act0 = (fmask >> (2 * wm)) & 1u;
        const bool act1 = (fmask >> (2 * wm + 1)) & 1u;

        asm volatile("cp.async.wait_group 0;\n" ::: "memory");
        __syncthreads();
        if (t + 1 < nact) {
            int o = s_sal[t + 1];
            unsigned dA = sAu + (unsigned)((b ^ 1) * ATILE);
            unsigned dB = sBu + (unsigned)((b ^ 1) * BTILE);
            if ((s_fmask[o] >> afrag) & 1u) {
                int id = sidx[o * BM + arow];
                unsigned ssz = (id >= 0) ? 16u : 0u;
                const __half* srcA = xin + (size_t)(id >= 0 ? id : 0) * CCH + ac0 * 8;
#pragma unroll
                for (int q = 0; q < 8; ++q)
                    cp16z(dA + swz(arow, ac0 + q), srcA + q * 8, ssz);
            }
            const __half* srcB = W + (size_t)o * CCH * CCH + brow * CCH + bc0 * 8;
#pragma unroll
            for (int q = 0; q < 4; ++q)
                cp16 (dB + swz(brow, bc0 + q), srcB + q * 8);
            asm volatile("cp.async.commit_group;\n" ::: "memory");
        }

        if (act0 | act1) {
            const unsigned Ab = sAu + (unsigned)(b * ATILE);
            const unsigned Bb = sBu + (unsigned)(b * BTILE);
#pragma unroll
            for (int kc = 0; kc < 8; ++kc) {
                uint32_t a[2][4];
                if (act0) {
                    int row = wm * 32 + (lane & 15);
                    ldsm_x4(a[0], Ab + swz(row, kc * 2 + (lane >> 4)));
                }
                if (act1) {
                    int row = wm * 32 + 16 + (lane & 15);
                    ldsm_x4(a[1], Ab + swz(row, kc * 2 + (lane >> 4)));
                }
#pragma unroll
                for (int nb = 0; nb < 4; ++nb) {
                    uint32_t bb[4];
                    int row = kc * 16 + (lane & 15);
                    ldsm_x4_t(bb, Bb + swz(row, wn * 8 + nb * 2 + (lane >> 4)));
                    if (act0) {
                        mma_f16(acc[0][nb * 2 + 0], a[0], bb[0], bb[1]);
                        mma_f16(acc[0][nb * 2 + 1], a[0], bb[2], bb[3]);
                    }
                    if (act1) {
                        mma_f16(acc[1][nb * 2 + 0], a[1], bb[0], bb[1]);
                        mma_f16(acc[1][nb * 2 + 1], a[1], bb[2], bb[3]);
                    }
                }
            }
        }
        __syncthreads();
    }

    // ---- BN partials (fp32, pre-quantization) --------------------------------
    const int cbase = wn * 64 + (lane & 3) * 2;
#pragma unroll
    for (int ni = 0; ni < 8; ++ni) {
#pragma unroll
        for (int tt = 0; tt < 2; ++tt) {
            float a0 = acc[0][ni][tt],     a1 = acc[0][ni][2 + tt];
            float a2 = acc[1][ni][tt],     a3 = acc[1][ni][2 + tt];
            float s = a0 + a1 + a2 + a3;
            float q = a0 * a0 + a1 * a1 + a2 * a2 + a3 * a3;
#pragma unroll
            for (int off = 4; off <= 16; off <<= 1) {
                s += __shfl_xor_sync(0xffffffffu, s, off);
                q += __shfl_xor_sync(0xffffffffu, q, off);
            }
            if ((lane >> 2) == 0) {
                int c = cbase + ni * 8 + tt;
                atomicAdd(&sstat[c], s);
                atomicAdd(&ssq[c], q);
            }
        }
    }

    // ---- epilogue: stage fp16 tile in smem (mainloop buffers are dead) -------
    // pitch 136 halfs (272B) -> conflict-free half2 writes; then coalesced copy.
    __half* ytile = (__half*)smem_raw;   // 256 x 136 halfs = 69,632B
    const int rrel = wm * 32 + (lane >> 2);
#pragma unroll
    for (int mi = 0; mi < 2; ++mi) {
#pragma unroll
        for (int ni = 0; ni < 8; ++ni) {
            int col = cbase + ni * 8;
            int r0 = rrel + mi * 16;
            *(__half2*)(ytile + r0 * YPITCH + col) =
                __floats2half2_rn(acc[mi][ni][0], acc[mi][ni][1]);
            *(__half2*)(ytile + (r0 + 8) * YPITCH + col) =
                __floats2half2_rn(acc[mi][ni][2], acc[mi][ni][3]);
        }
    }
    __syncthreads();
    // coalesced copy out: 256 rows x 16 chunks of 16B, full sectors
    for (int ch = tid; ch < 4096; ch += 512) {
        int row = ch >> 4, c16 = ch & 15;
        int gv = v0 + row;
        if (gv < M) {
            uint4 val = *(const uint4*)(ytile + row * YPITCH + c16 * 8);
            *(uint4*)(y + (size_t)gv * CCH + c16 * 8) = val;
        }
    }
    if (tid < CCH) {
        atomicAdd(&gstats[tid],       sstat[tid]);
        atomicAdd(&gstats[CCH + tid], ssq[tid]);
    }
}

// ---------------- BN apply: hoisted scale/bias, uint4 fp16 in/out -------------
__global__ __launch_bounds__(256)
void bn_apply_kernel(const __half* __restrict__ y,     // fp16 conv output
                     const float* __restrict__ g,
                     const float* __restrict__ b,
                     const float* __restrict__ stats,
                     const __half* __restrict__ residual,   // nullable (fp16)
                     __half* __restrict__ out_h16,
                     int M) {
    __shared__ float sc[CCH], sb[CCH];
    float invM = 1.f / (float)M;
    if (threadIdx.x < CCH) {
        int c = threadIdx.x;
        float m   = stats[c] * invM;
        float var = stats[128 + c] * invM - m * m;
        float s = rsqrtf(var + EPSV) * g[c];
        sc[c] = s;
        sb[c] = b[c] - m * s;
    }
    __syncthreads();

    int total8 = M * 16;   // groups of 8 channels (16B)
    for (int i = blockIdx.x * blockDim.x + threadIdx.x; i < total8; i += gridDim.x * blockDim.x) {
        int c0 = (i & 15) * 8;
        uint4 yv = ((const uint4*)y)[i];
        float2 p0 = __half22float2(*(__half2*)&yv.x);
        float2 p1 = __half22float2(*(__half2*)&yv.y);
        float2 p2 = __half22float2(*(__half2*)&yv.z);
        float2 p3 = __half22float2(*(__half2*)&yv.w);
        float v[8] = {p0.x, p0.y, p1.x, p1.y, p2.x, p2.y, p3.x, p3.y};
#pragma unroll
        for (int q = 0; q < 8; ++q) v[q] = v[q] * sc[c0 + q] + sb[c0 + q];
        if (residual) {
            uint4 rv = ((const uint4*)residual)[i];
            float2 r0 = __half22float2(*(__half2*)&rv.x);
            float2 r1 = __half22float2(*(__half2*)&rv.y);
            float2 r2 = __half22float2(*(__half2*)&rv.z);
            float2 r3 = __half22float2(*(__half2*)&rv.w);
            v[0] += r0.x; v[1] += r0.y; v[2] += r1.x; v[3] += r1.y;
            v[4] += r2.x; v[5] += r2.y; v[6] += r3.x; v[7] += r3.y;
        }
#pragma unroll
        for (int q = 0; q < 8; ++q) v[q] = fmaxf(v[q], 0.f);
        uint4 ov;
        *(__half2*)&ov.x = __floats2half2_rn(v[0], v[1]);
        *(__half2*)&ov.y = __floats2half2_rn(v[2], v[3]);
        *(__half2*)&ov.z = __floats2half2_rn(v[4], v[5]);
        *(__half2*)&ov.w = __floats2half2_rn(v[6], v[7]);
        ((uint4*)out_h16)[i] = ov;
    }
}

// ---------------- head on voxels: dvox = relu(x@w1+b1)@w2 + b2 ----------------
__global__ __launch_bounds__(256)
void head_vox_kernel(const __half* __restrict__ xh,
                     const __half* __restrict__ w1h,
                     const float* __restrict__ b1,
                     const float* __restrict__ w2,
                     const float* __restrict__ b2,
                     float* __restrict__ dvox,
                     int M) {
    extern __shared__ __align__(16) char smem_raw[];
    float* hs = (float*)(smem_raw + 49152);
    __shared__ float b1s[64], b2s[14], w2s[64 * 14];

    const int tid  = threadIdx.x;
    const int warp = tid >> 5, lane = tid & 31;
    const int v0 = blockIdx.x * 128;

    const unsigned sAu = smem_u32(smem_raw);
    const unsigned sBu = sAu + 32768u;

    {
        int row = tid >> 1, c0 = (tid & 1) * 8;
        unsigned ssz = (v0 + row < M) ? 16u : 0u;
        const __half* srcA = xh + (size_t)(v0 + row < M ? v0 + row : 0) * CCH + c0 * 8;
#pragma unroll
        for (int q = 0; q < 8; ++q)
            cp16z(sAu + swz(row, c0 + q), srcA + q * 8, ssz);
    }
    for (int j = tid; j < 1024; j += 256) {
        int row = j >> 3, c = j & 7;
        cp16(sBu + swz64(row, c), w1h + row * 64 + c * 8);
    }
    asm volatile("cp.async.commit_group;\n" ::: "memory");
    if (tid < 64) b1s[tid] = b1[tid];
    if (tid < 14) b2s[tid] = b2[tid];
    for (int j = tid; j < 64 * 14; j += 256) w2s[j] = w2[j];
    asm volatile("cp.async.wait_group 0;\n" ::: "memory");
    __syncthreads();

    float acc[8][4];
#pragma unroll
    for (int ni = 0; ni < 8; ++ni)
#pragma unroll
        for (int q = 0; q < 4; ++q) acc[ni][q] = 0.f;
#pragma unroll
    for (int kc = 0; kc < 8; ++kc) {
        uint32_t a[4];
        ldsm_x4(a, sAu + swz(warp * 16 + (lane & 15), kc * 2 + (lane >> 4)));
#pragma unroll
        for (int nb = 0; nb < 4; ++nb) {
            uint32_t bb[4];
            ldsm_x4_t(bb, sBu + swz64(kc * 16 + (lane & 15), nb * 2 + (lane >> 4)));
            mma_f16(acc[nb * 2 + 0], a, bb[0], bb[1]);
            mma_f16(acc[nb * 2 + 1], a, bb[2], bb[3]);
        }
    }
    {
        int r0 = warp * 16 + (lane >> 2);
        int c0 = (lane & 3) * 2;
#pragma unroll
        for (int ni = 0; ni < 8; ++ni) {
            int c = c0 + ni * 8;
            hs[r0 * 65 + c]           = fmaxf(acc[ni][0] + b1s[c], 0.f);
            hs[r0 * 65 + c + 1]       = fmaxf(acc[ni][1] + b1s[c + 1], 0.f);
            hs[(r0 + 8) * 65 + c]     = fmaxf(acc[ni][2] + b1s[c], 0.f);
            hs[(r0 + 8) * 65 + c + 1] = fmaxf(acc[ni][3] + b1s[c + 1], 0.f);
        }
    }
    __syncthreads();

    {
        int r = tid >> 1;
        int cb = (tid & 1) * 7;
        if (v0 + r < M) {
            float d[7];
#pragma unroll
            for (int c = 0; c < 7; ++c) d[c] = b2s[cb + c];
#pragma unroll 8
            for (int k = 0; k < 64; ++k) {
                float hv = hs[r * 65 + k];
#pragma unroll
                for (int c = 0; c < 7; ++c) d[c] += hv * w2s[k * 14 + cb + c];
            }
            float* dst = dvox + (size_t)(v0 + r) * 14 + cb;
#pragma unroll
            for (int c = 0; c < 7; ++c) dst[c] = d[c];
        }
    }
}

// ---------------- scatter: out = gp + dvox[inv_idx], thread-per-point ---------
__global__ void scatter_out_kernel(const float* __restrict__ gp,
                                   const float* __restrict__ dvox,
                                   const int*   __restrict__ inv_idx,
                                   float* __restrict__ out, int Np) {
    for (int i = blockIdx.x * blockDim.x + threadIdx.x; i < Np; i += gridDim.x * blockDim.x) {
        const float* dr = dvox + (size_t)inv_idx[i] * 14;
        const float* gr = gp + (size_t)i * 14;
        float* orow = out + (size_t)i * 14;
#pragma unroll
        for (int j = 0; j < 14; ++j) orow[j] = gr[j] + dr[j];
    }
}

// ---------------- launch -------------------------------------------------------
extern "C" void kernel_launch(void* const* d_in, const int* in_sizes, int n_in,
                              void* d_out, int out_size) {
    const float* gp       = (const float*)d_in[0];
    const float* w_enc    = (const float*)d_in[1];
    const float* b_enc    = (const float*)d_in[2];
    const float* ln_g     = (const float*)d_in[3];
    const float* ln_b     = (const float*)d_in[4];
    const float* conv_w   = (const float*)d_in[5];
    const float* bn_g     = (const float*)d_in[6];
    const float* bn_b     = (const float*)d_in[7];
    const float* w1       = (const float*)d_in[8];
    const float* b1       = (const float*)d_in[9];
    const float* w2       = (const float*)d_in[10];
    const float* b2       = (const float*)d_in[11];
    const float* nbr_mask = (const float*)d_in[12];
    const int*   inv_idx  = (const int*)d_in[13];
    const int*   nbr_idx  = (const int*)d_in[14];
    float* out = (float*)d_out;

    const int Np = in_sizes[0] / 14;
    const int M  = in_sizes[12] / 27;

    float *px, *pdv, *pcnt, *pstats;
    __half *pyh, *pxh, *pah, *pwh, *pw1h;
    cudaGetSymbolAddress((void**)&px,     g_x);
    cudaGetSymbolAddress((void**)&pdv,    g_dv);
    cudaGetSymbolAddress((void**)&pyh,    g_yh);
    cudaGetSymbolAddress((void**)&pxh,    g_xh);
    cudaGetSymbolAddress((void**)&pah,    g_ah);
    cudaGetSymbolAddress((void**)&pwh,    g_wh);
    cudaGetSymbolAddress((void**)&pw1h,   g_w1h);
    cudaGetSymbolAddress((void**)&pcnt,   g_cnt);
    cudaGetSymbolAddress((void**)&pstats, g_stats);

    const int CONV_SMEM = 2 * ATILE + 2 * BTILE + 27 * BM * 4;  // 224256
    cudaFuncSetAttribute(subm_conv_mma_kernel,
                         cudaFuncAttributeMaxDynamicSharedMemorySize, CONV_SMEM);
    const int HEAD_SMEM = 49152 + 128 * 65 * 4;                 // 82432
    cudaFuncSetAttribute(head_vox_kernel,
                         cudaFuncAttributeMaxDynamicSharedMemorySize, HEAD_SMEM);

    convert_w_kernel<<<1024, 256>>>(conv_w, pwh, 4 * 27 * CCH * CCH);
    convert_w_kernel<<<8, 256>>>(w1, pw1h, CCH * 64);
    cudaMemsetAsync(px, 0, (size_t)M * CCH * sizeof(float));
    cudaMemsetAsync(pcnt, 0, (size_t)M * sizeof(float));
    encode_pool_kernel<<<512, 256>>>(gp, w_enc, b_enc, ln_g, ln_b, inv_idx, px, pcnt, Np);
    pool_div_kernel<<<2048, 256>>>(px, pcnt, pxh, M);

    const int tiles = (M + BM - 1) / BM;
    for (int blk = 0; blk < 2; ++blk) {
        const int l0 = 2 * blk, l1 = 2 * blk + 1;
        // conv1 (fused BN stats, fp16 y) -> BN apply -> ReLU (fp16 out)
        cudaMemsetAsync(pstats, 0, 256 * sizeof(float));
        subm_conv_mma_kernel<<<tiles, 512, CONV_SMEM>>>(
            pxh, pwh + (size_t)l0 * 27 * CCH * CCH, nbr_idx, nbr_mask, pyh, pstats, M);
        bn_apply_kernel<<<2048, 256>>>(pyh, bn_g + l0 * CCH, bn_b + l0 * CCH, pstats,
                                       (const __half*)0, pah, M);
        // conv2 (fused BN stats, fp16 y) -> BN apply + fp16 residual (in-place xh)
        cudaMemsetAsync(pstats, 0, 256 * sizeof(float));
        subm_conv_mma_kernel<<<tiles, 512, CONV_SMEM>>>(
            pah, pwh + (size_t)l1 * 27 * CCH * CCH, nbr_idx, nbr_mask, pyh, pstats, M);
        bn_apply_kernel<<<2048, 256>>>(pyh, bn_g + l1 * CCH, bn_b + l1 * CCH, pstats,
                                       pxh, pxh, M);
    }

    head_vox_kernel<<<(M + 127) / 128, 256, HEAD_SMEM>>>(pxh, pw1h, b1, w2, b2, pdv, M);
    scatter_out_kernel<<<1024, 256>>>(gp, pdv, inv_idx, out, Np);
}

// round 15
// speedup vs baseline: 1.5506x; 1.0244x over previous
#include <cuda_runtime.h>
#include <cuda_fp16.h>
#include <stdint.h>
#include <math.h>

#define NPTS 200000
#define CCH  128
#define EPSV 1e-5f
#define ATILE 65536u            // 256 x 128 halfs, swizzled
#define BTILE 32768u            // 128 x 128 halfs, swizzled
#define BM    256
#define YPITCH 136              // halfs per row in epilogue staging (272B)

// ---------------- scratch (device globals; no allocations anywhere) ----------
__device__ float  g_x[NPTS * CCH];           // fp32 pooled sums (encoder)
__device__ float  g_dv[NPTS * 14];           // fp32 dvox (head output)
__device__ __half g_yh[NPTS * CCH];          // fp16 conv output
__device__ __half g_xh[NPTS * CCH];          // fp16 x path (input / residual)
__device__ __half g_ah[NPTS * CCH];          // fp16 mid path
__device__ __half g_wh[4 * 27 * CCH * CCH];  // fp16 conv weights
__device__ __half g_w1h[CCH * 64];           // fp16 head weights
__device__ float  g_cnt[NPTS];
__device__ float  g_stats[256];              // [0..127]=sum [128..255]=sumsq

// ---------------- helpers ----------------
__device__ __forceinline__ unsigned smem_u32(const void* p) {
    return (unsigned)__cvta_generic_to_shared(p);
}
__device__ __forceinline__ unsigned swz(int row, int c16) {
    return (unsigned)(row * 256 + (((c16) ^ (row & 7)) << 4));
}
__device__ __forceinline__ unsigned swz64(int row, int c16) {
    return (unsigned)(row * 128 + (((c16) ^ (row & 7)) << 4));
}
__device__ __forceinline__ void ldsm_x4(uint32_t* r, unsigned addr) {
    asm volatile("ldmatrix.sync.aligned.m8n8.x4.shared.b16 {%0,%1,%2,%3}, [%4];\n"
                 : "=r"(r[0]), "=r"(r[1]), "=r"(r[2]), "=r"(r[3]) : "r"(addr));
}
__device__ __forceinline__ void ldsm_x4_t(uint32_t* r, unsigned addr) {
    asm volatile("ldmatrix.sync.aligned.m8n8.x4.trans.shared.b16 {%0,%1,%2,%3}, [%4];\n"
                 : "=r"(r[0]), "=r"(r[1]), "=r"(r[2]), "=r"(r[3]) : "r"(addr));
}
__device__ __forceinline__ void mma_f16(float* c, const uint32_t* a, uint32_t b0, uint32_t b1) {
    asm volatile("mma.sync.aligned.m16n8k16.row.col.f32.f16.f16.f32 "
                 "{%0,%1,%2,%3}, {%4,%5,%6,%7}, {%8,%9}, {%0,%1,%2,%3};\n"
                 : "+f"(c[0]), "+f"(c[1]), "+f"(c[2]), "+f"(c[3])
                 : "r"(a[0]), "r"(a[1]), "r"(a[2]), "r"(a[3]), "r"(b0), "r"(b1));
}
__device__ __forceinline__ void cp16(unsigned dst, const void* src) {
    asm volatile("cp.async.cg.shared.global [%0], [%1], 16;\n" :: "r"(dst), "l"(src));
}
__device__ __forceinline__ void cp16z(unsigned dst, const void* src, unsigned ssz) {
    asm volatile("cp.async.cg.shared.global [%0], [%1], 16, %2;\n"
                 :: "r"(dst), "l"(src), "r"(ssz));
}

// ---------------- weight fp32 -> fp16 ----------------
__global__ void convert_w_kernel(const float* __restrict__ w, __half* __restrict__ wh, int n) {
    for (int i = blockIdx.x * blockDim.x + threadIdx.x; i < n; i += gridDim.x * blockDim.x)
        wh[i] = __float2half(w[i]);
}

// ---------------- pass 1: per-voxel point counts ------------------------------
__global__ void count_kernel(const int* __restrict__ inv_idx, float* __restrict__ cnt, int Np) {
    for (int i = blockIdx.x * blockDim.x + threadIdx.x; i < Np; i += gridDim.x * blockDim.x)
        atomicAdd(&cnt[inv_idx[i]], 1.f);
}

// ---------------- encoder: warp-per-point; plain stores for singleton voxels --
__global__ __launch_bounds__(256)
void encode_pool_kernel(const float* __restrict__ gp,
                        const float* __restrict__ w_enc,
                        const float* __restrict__ b_enc,
                        const float* __restrict__ ln_g,
                        const float* __restrict__ ln_b,
                        const int*   __restrict__ inv_idx,
                        const float* __restrict__ cnt,
                        float* __restrict__ xsum,
                        int Np) {
    const int lane = threadIdx.x & 31;
    const int gw = (blockIdx.x * blockDim.x + threadIdx.x) >> 5;
    const int nw = (gridDim.x * blockDim.x) >> 5;
    const int c0 = lane * 4;

    float wreg[14][4];
#pragma unroll
    for (int k = 0; k < 14; ++k) {
        float4 t = *(const float4*)(w_enc + k * CCH + c0);
        wreg[k][0] = t.x; wreg[k][1] = t.y; wreg[k][2] = t.z; wreg[k][3] = t.w;
    }
    float4 be = *(const float4*)(b_enc + c0);
    float4 lg = *(const float4*)(ln_g + c0);
    float4 lb = *(const float4*)(ln_b + c0);

    for (int i = gw; i < Np; i += nw) {
        float gv = (lane < 14) ? gp[(size_t)i * 14 + lane] : 0.f;
        float f0 = be.x, f1 = be.y, f2 = be.z, f3 = be.w;
#pragma unroll
        for (int k = 0; k < 14; ++k) {
            float s = __shfl_sync(0xffffffffu, gv, k);
            f0 += s * wreg[k][0]; f1 += s * wreg[k][1];
            f2 += s * wreg[k][2]; f3 += s * wreg[k][3];
        }
        float s1 = f0 + f1 + f2 + f3;
        float s2 = f0 * f0 + f1 * f1 + f2 * f2 + f3 * f3;
#pragma unroll
        for (int off = 16; off > 0; off >>= 1) {
            s1 += __shfl_xor_sync(0xffffffffu, s1, off);
            s2 += __shfl_xor_sync(0xffffffffu, s2, off);
        }
        float mu  = s1 * (1.f / 128.f);
        float inv = rsqrtf(s2 * (1.f / 128.f) - mu * mu + EPSV);
        int vox = inv_idx[i];
        float v0 = fmaxf((f0 - mu) * inv * lg.x + lb.x, 0.f);
        float v1 = fmaxf((f1 - mu) * inv * lg.y + lb.y, 0.f);
        float v2 = fmaxf((f2 - mu) * inv * lg.z + lb.z, 0.f);
        float v3 = fmaxf((f3 - mu) * inv * lg.w + lb.w, 0.f);
        float* dst = xsum + (size_t)vox * CCH + c0;
        if (cnt[vox] == 1.f) {
            // sole owner: plain vectorized store (no race)
            *(float4*)dst = make_float4(v0, v1, v2, v3);
        } else {
            atomicAdd(dst + 0, v0);
            atomicAdd(dst + 1, v1);
            atomicAdd(dst + 2, v2);
            atomicAdd(dst + 3, v3);
        }
    }
}

// ---------------- pooled sums / counts -> fp16, vectorized --------------------
__global__ void pool_div_kernel(const float* __restrict__ x, const float* __restrict__ cnt,
                                __half* __restrict__ xh, int M) {
    int total4 = M * 32;   // float4 groups
    for (int i = blockIdx.x * blockDim.x + threadIdx.x; i < total4; i += gridDim.x * blockDim.x) {
        float inv = 1.f / cnt[i >> 5];
        float4 v = ((const float4*)x)[i];
        ((__half2*)xh)[2 * i]     = __floats2half2_rn(v.x * inv, v.y * inv);
        ((__half2*)xh)[2 * i + 1] = __floats2half2_rn(v.z * inv, v.w * inv);
    }
}

// ---------------- submanifold conv, fp16 mma.sync, cp.async double-buffered ---
// 256x128 tile / 512 threads (16 warps, 8x2). Fragment-activity skip (exact).
// BN sum/sumsq fp32 from registers; fp16 y via smem staging (full sectors).
__global__ __launch_bounds__(512, 1)
void subm_conv_mma_kernel(const __half* __restrict__ xin,
                          const __half* __restrict__ W,   // 27 x 128 x 128 fp16
                          const int*   __restrict__ nbr_idx,
                          const float* __restrict__ nbr_mask,
                          __half* __restrict__ y,          // fp16 out
                          float* __restrict__ gstats,
                          int M) {
    extern __shared__ __align__(16) char smem_raw[];
    int* sidx = (int*)(smem_raw + 2 * ATILE + 2 * BTILE);   // 27 x 256
    __shared__ unsigned s_fmask[27];
    __shared__ int   s_sal[27], s_nact;
    __shared__ float sstat[CCH], ssq[CCH];

    const int tid  = threadIdx.x;
    const int warp = tid >> 5, lane = tid & 31;
    const int wm = warp >> 1;
    const int wn = warp & 1;
    const int v0 = blockIdx.x * BM;

    for (int j = tid; j < 27 * BM; j += 512) {
        int r = j / 27, o = j - r * 27;
        int v = v0 + r;
        int id = -1;
        if (v < M && nbr_mask[(size_t)v0 * 27 + j] != 0.f)
            id = nbr_idx[(size_t)v0 * 27 + j];
        sidx[o * BM + r] = id;
    }
    if (tid < 27) s_fmask[tid] = 0u;
    if (tid < CCH) { sstat[tid] = 0.f; ssq[tid] = 0.f; }
    __syncthreads();
    if (tid < 432) {
        int o = tid >> 4, f = tid & 15;
        const int* p = sidx + o * BM + f * 16;
        int any = 0;
#pragma unroll
        for (int i = 0; i < 16; ++i) any |= (p[i] >= 0);
        if (any) atomicOr(&s_fmask[o], 1u << f);
    }
    __syncthreads();
    if (tid == 0) {
        int n = 0;
        for (int o = 0; o < 27; ++o) if (s_fmask[o]) s_sal[n++] = o;
        s_nact = n;
    }
    __syncthreads();
    const int nact = s_nact;

    const unsigned sAu = smem_u32(smem_raw);
    const unsigned sBu = sAu + 2 * ATILE;
    const int arow = tid >> 1;
    const int ac0  = (tid & 1) * 8;
    const int afrag = arow >> 4;
    const int brow = tid >> 2;
    const int bc0  = (tid & 3) * 4;

    float acc[2][8][4];
#pragma unroll
    for (int mi = 0; mi < 2; ++mi)
#pragma unroll
        for (int ni = 0; ni < 8; ++ni)
#pragma unroll
            for (int q = 0; q < 4; ++q) acc[mi][ni][q] = 0.f;

    {   // stage offset 0 into buffer 0
        int o = s_sal[0];
        if ((s_fmask[o] >> afrag) & 1u) {
            int id = sidx[o * BM + arow];
            unsigned ssz = (id >= 0) ? 16u : 0u;
            const __half* srcA = xin + (size_t)(id >= 0 ? id : 0) * CCH + ac0 * 8;
#pragma unroll
            for (int q = 0; q < 8; ++q)
                cp16z(sAu + swz(arow, ac0 + q), srcA + q * 8, ssz);
        }
        const __half* srcB = W + (size_t)o * CCH * CCH + brow * CCH + bc0 * 8;
#pragma unroll
        for (int q = 0; q < 4; ++q)
            cp16 (sBu + swz(brow, bc0 + q), srcB + q * 8);
        asm volatile("cp.async.commit_group;\n" ::: "memory");
    }

    for (int t = 0; t < nact; ++t) {
        const int b = t & 1;
        const unsigned fmask = s_fmask[s_sal[t]];
        const bool act0 = (fmask >> (2 * wm)) & 1u;
        const bool act1 = (fmask >> (2 * wm + 1)) & 1u;

        asm volatile("cp.async.wait_group 0;\n" ::: "memory");
        __syncthreads();
        if (t + 1 < nact) {
            int o = s_sal[t + 1];
            unsigned dA = sAu + (unsigned)((b ^ 1) * ATILE);
            unsigned dB = sBu + (unsigned)((b ^ 1) * BTILE);
            if ((s_fmask[o] >> afrag) & 1u) {
                int id = sidx[o * BM + arow];
                unsigned ssz = (id >= 0) ? 16u : 0u;
                const __half* srcA = xin + (size_t)(id >= 0 ? id : 0) * CCH + ac0 * 8;
#pragma unroll
                for (int q = 0; q < 8; ++q)
                    cp16z(dA + swz(arow, ac0 + q), srcA + q * 8, ssz);
            }
            const __half* srcB = W + (size_t)o * CCH * CCH + brow * CCH + bc0 * 8;
#pragma unroll
            for (int q = 0; q < 4; ++q)
                cp16 (dB + swz(brow, bc0 + q), srcB + q * 8);
            asm volatile("cp.async.commit_group;\n" ::: "memory");
        }

        if (act0 | act1) {
            const unsigned Ab = sAu + (unsigned)(b * ATILE);
            const unsigned Bb = sBu + (unsigned)(b * BTILE);
#pragma unroll
            for (int kc = 0; kc < 8; ++kc) {
                uint32_t a[2][4];
                if (act0) {
                    int row = wm * 32 + (lane & 15);
                    ldsm_x4(a[0], Ab + swz(row, kc * 2 + (lane >> 4)));
                }
                if (act1) {
                    int row = wm * 32 + 16 + (lane & 15);
                    ldsm_x4(a[1], Ab + swz(row, kc * 2 + (lane >> 4)));
                }
#pragma unroll
                for (int nb = 0; nb < 4; ++nb) {
                    uint32_t bb[4];
                    int row = kc * 16 + (lane & 15);
                    ldsm_x4_t(bb, Bb + swz(row, wn * 8 + nb * 2 + (lane >> 4)));
                    if (act0) {
                        mma_f16(acc[0][nb * 2 + 0], a[0], bb[0], bb[1]);
                        mma_f16(acc[0][nb * 2 + 1], a[0], bb[2], bb[3]);
                    }
                    if (act1) {
                        mma_f16(acc[1][nb * 2 + 0], a[1], bb[0], bb[1]);
                        mma_f16(acc[1][nb * 2 + 1], a[1], bb[2], bb[3]);
                    }
                }
            }
        }
        __syncthreads();
    }

    // ---- BN partials (fp32, pre-quantization) --------------------------------
    const int cbase = wn * 64 + (lane & 3) * 2;
#pragma unroll
    for (int ni = 0; ni < 8; ++ni) {
#pragma unroll
        for (int tt = 0; tt < 2; ++tt) {
            float a0 = acc[0][ni][tt],     a1 = acc[0][ni][2 + tt];
            float a2 = acc[1][ni][tt],     a3 = acc[1][ni][2 + tt];
            float s = a0 + a1 + a2 + a3;
            float q = a0 * a0 + a1 * a1 + a2 * a2 + a3 * a3;
#pragma unroll
            for (int off = 4; off <= 16; off <<= 1) {
                s += __shfl_xor_sync(0xffffffffu, s, off);
                q += __shfl_xor_sync(0xffffffffu, q, off);
            }
            if ((lane >> 2) == 0) {
                int c = cbase + ni * 8 + tt;
                atomicAdd(&sstat[c], s);
                atomicAdd(&ssq[c], q);
            }
        }
    }

    // ---- epilogue: stage fp16 tile in smem, then coalesced full-sector copy --
    __half* ytile = (__half*)smem_raw;   // 256 x 136 halfs
    const int rrel = wm * 32 + (lane >> 2);
#pragma unroll
    for (int mi = 0; mi < 2; ++mi) {
#pragma unroll
        for (int ni = 0; ni < 8; ++ni) {
            int col = cbase + ni * 8;
            int r0 = rrel + mi * 16;
            *(__half2*)(ytile + r0 * YPITCH + col) =
                __floats2half2_rn(acc[mi][ni][0], acc[mi][ni][1]);
            *(__half2*)(ytile + (r0 + 8) * YPITCH + col) =
                __floats2half2_rn(acc[mi][ni][2], acc[mi][ni][3]);
        }
    }
    __syncthreads();
    for (int ch = tid; ch < 4096; ch += 512) {
        int row = ch >> 4, c16 = ch & 15;
        int gv = v0 + row;
        if (gv < M) {
            uint4 val = *(const uint4*)(ytile + row * YPITCH + c16 * 8);
            *(uint4*)(y + (size_t)gv * CCH + c16 * 8) = val;
        }
    }
    if (tid < CCH) {
        atomicAdd(&gstats[tid],       sstat[tid]);
        atomicAdd(&gstats[CCH + tid], ssq[tid]);
    }
}

// ---------------- BN apply: hoisted scale/bias, uint4 fp16 in/out -------------
__global__ __launch_bounds__(256)
void bn_apply_kernel(const __half* __restrict__ y,
                     const float* __restrict__ g,
                     const float* __restrict__ b,
                     const float* __restrict__ stats,
                     const __half* __restrict__ residual,   // nullable (fp16)
                     __half* __restrict__ out_h16,
                     int M) {
    __shared__ float sc[CCH], sb[CCH];
    float invM = 1.f / (float)M;
    if (threadIdx.x < CCH) {
        int c = threadIdx.x;
        float m   = stats[c] * invM;
        float var = stats[128 + c] * invM - m * m;
        float s = rsqrtf(var + EPSV) * g[c];
        sc[c] = s;
        sb[c] = b[c] - m * s;
    }
    __syncthreads();

    int total8 = M * 16;
    for (int i = blockIdx.x * blockDim.x + threadIdx.x; i < total8; i += gridDim.x * blockDim.x) {
        int c0 = (i & 15) * 8;
        uint4 yv = ((const uint4*)y)[i];
        float2 p0 = __half22float2(*(__half2*)&yv.x);
        float2 p1 = __half22float2(*(__half2*)&yv.y);
        float2 p2 = __half22float2(*(__half2*)&yv.z);
        float2 p3 = __half22float2(*(__half2*)&yv.w);
        float v[8] = {p0.x, p0.y, p1.x, p1.y, p2.x, p2.y, p3.x, p3.y};
#pragma unroll
        for (int q = 0; q < 8; ++q) v[q] = v[q] * sc[c0 + q] + sb[c0 + q];
        if (residual) {
            uint4 rv = ((const uint4*)residual)[i];
            float2 r0 = __half22float2(*(__half2*)&rv.x);
            float2 r1 = __half22float2(*(__half2*)&rv.y);
            float2 r2 = __half22float2(*(__half2*)&rv.z);
            float2 r3 = __half22float2(*(__half2*)&rv.w);
            v[0] += r0.x; v[1] += r0.y; v[2] += r1.x; v[3] += r1.y;
            v[4] += r2.x; v[5] += r2.y; v[6] += r3.x; v[7] += r3.y;
        }
#pragma unroll
        for (int q = 0; q < 8; ++q) v[q] = fmaxf(v[q], 0.f);
        uint4 ov;
        *(__half2*)&ov.x = __floats2half2_rn(v[0], v[1]);
        *(__half2*)&ov.y = __floats2half2_rn(v[2], v[3]);
        *(__half2*)&ov.z = __floats2half2_rn(v[4], v[5]);
        *(__half2*)&ov.w = __floats2half2_rn(v[6], v[7]);
        ((uint4*)out_h16)[i] = ov;
    }
}

// ---------------- head on voxels: dvox = relu(x@w1+b1)@w2 + b2 ----------------
__global__ __launch_bounds__(256)
void head_vox_kernel(const __half* __restrict__ xh,
                     const __half* __restrict__ w1h,
                     const float* __restrict__ b1,
                     const float* __restrict__ w2,
                     const float* __restrict__ b2,
                     float* __restrict__ dvox,
                     int M) {
    extern __shared__ __align__(16) char smem_raw[];
    float* hs = (float*)(smem_raw + 49152);
    __shared__ float b1s[64], b2s[14], w2s[64 * 14];

    const int tid  = threadIdx.x;
    const int warp = tid >> 5, lane = tid & 31;
    const int v0 = blockIdx.x * 128;

    const unsigned sAu = smem_u32(smem_raw);
    const unsigned sBu = sAu + 32768u;

    {
        int row = tid >> 1, c0 = (tid & 1) * 8;
        unsigned ssz = (v0 + row < M) ? 16u : 0u;
        const __half* srcA = xh + (size_t)(v0 + row < M ? v0 + row : 0) * CCH + c0 * 8;
#pragma unroll
        for (int q = 0; q < 8; ++q)
            cp16z(sAu + swz(row, c0 + q), srcA + q * 8, ssz);
    }
    for (int j = tid; j < 1024; j += 256) {
        int row = j >> 3, c = j & 7;
        cp16(sBu + swz64(row, c), w1h + row * 64 + c * 8);
    }
    asm volatile("cp.async.commit_group;\n" ::: "memory");
    if (tid < 64) b1s[tid] = b1[tid];
    if (tid < 14) b2s[tid] = b2[tid];
    for (int j = tid; j < 64 * 14; j += 256) w2s[j] = w2[j];
    asm volatile("cp.async.wait_group 0;\n" ::: "memory");
    __syncthreads();

    float acc[8][4];
#pragma unroll
    for (int ni = 0; ni < 8; ++ni)
#pragma unroll
        for (int q = 0; q < 4; ++q) acc[ni][q] = 0.f;
#pragma unroll
    for (int kc = 0; kc < 8; ++kc) {
        uint32_t a[4];
        ldsm_x4(a, sAu + swz(warp * 16 + (lane & 15), kc * 2 + (lane >> 4)));
#pragma unroll
        for (int nb = 0; nb < 4; ++nb) {
            uint32_t bb[4];
            ldsm_x4_t(bb, sBu + swz64(kc * 16 + (lane & 15), nb * 2 + (lane >> 4)));
            mma_f16(acc[nb * 2 + 0], a, bb[0], bb[1]);
            mma_f16(acc[nb * 2 + 1], a, bb[2], bb[3]);
        }
    }
    {
        int r0 = warp * 16 + (lane >> 2);
        int c0 = (lane & 3) * 2;
#pragma unroll
        for (int ni = 0; ni < 8; ++ni) {
            int c = c0 + ni * 8;
            hs[r0 * 65 + c]           = fmaxf(acc[ni][0] + b1s[c], 0.f);
            hs[r0 * 65 + c + 1]       = fmaxf(acc[ni][1] + b1s[c + 1], 0.f);
            hs[(r0 + 8) * 65 + c]     = fmaxf(acc[ni][2] + b1s[c], 0.f);
            hs[(r0 + 8) * 65 + c + 1] = fmaxf(acc[ni][3] + b1s[c + 1], 0.f);
        }
    }
    __syncthreads();

    {
        int r = tid >> 1;
        int cb = (tid & 1) * 7;
        if (v0 + r < M) {
            float d[7];
#pragma unroll
            for (int c = 0; c < 7; ++c) d[c] = b2s[cb + c];
#pragma unroll 8
            for (int k = 0; k < 64; ++k) {
                float hv = hs[r * 65 + k];
#pragma unroll
                for (int c = 0; c < 7; ++c) d[c] += hv * w2s[k * 14 + cb + c];
            }
            float* dst = dvox + (size_t)(v0 + r) * 14 + cb;
#pragma unroll
            for (int c = 0; c < 7; ++c) dst[c] = d[c];
        }
    }
}

// ---------------- scatter: out = gp + dvox[inv_idx], thread-per-point ---------
__global__ void scatter_out_kernel(const float* __restrict__ gp,
                                   const float* __restrict__ dvox,
                                   const int*   __restrict__ inv_idx,
                                   float* __restrict__ out, int Np) {
    for (int i = blockIdx.x * blockDim.x + threadIdx.x; i < Np; i += gridDim.x * blockDim.x) {
        const float* dr = dvox + (size_t)inv_idx[i] * 14;
        const float* gr = gp + (size_t)i * 14;
        float* orow = out + (size_t)i * 14;
#pragma unroll
        for (int j = 0; j < 14; ++j) orow[j] = gr[j] + dr[j];
    }
}

// ---------------- launch -------------------------------------------------------
extern "C" void kernel_launch(void* const* d_in, const int* in_sizes, int n_in,
                              void* d_out, int out_size) {
    const float* gp       = (const float*)d_in[0];
    const float* w_enc    = (const float*)d_in[1];
    const float* b_enc    = (const float*)d_in[2];
    const float* ln_g     = (const float*)d_in[3];
    const float* ln_b     = (const float*)d_in[4];
    const float* conv_w   = (const float*)d_in[5];
    const float* bn_g     = (const float*)d_in[6];
    const float* bn_b     = (const float*)d_in[7];
    const float* w1       = (const float*)d_in[8];
    const float* b1       = (const float*)d_in[9];
    const float* w2       = (const float*)d_in[10];
    const float* b2       = (const float*)d_in[11];
    const float* nbr_mask = (const float*)d_in[12];
    const int*   inv_idx  = (const int*)d_in[13];
    const int*   nbr_idx  = (const int*)d_in[14];
    float* out = (float*)d_out;

    const int Np = in_sizes[0] / 14;
    const int M  = in_sizes[12] / 27;

    float *px, *pdv, *pcnt, *pstats;
    __half *pyh, *pxh, *pah, *pwh, *pw1h;
    cudaGetSymbolAddress((void**)&px,     g_x);
    cudaGetSymbolAddress((void**)&pdv,    g_dv);
    cudaGetSymbolAddress((void**)&pyh,    g_yh);
    cudaGetSymbolAddress((void**)&pxh,    g_xh);
    cudaGetSymbolAddress((void**)&pah,    g_ah);
    cudaGetSymbolAddress((void**)&pwh,    g_wh);
    cudaGetSymbolAddress((void**)&pw1h,   g_w1h);
    cudaGetSymbolAddress((void**)&pcnt,   g_cnt);
    cudaGetSymbolAddress((void**)&pstats, g_stats);

    const int CONV_SMEM = 2 * ATILE + 2 * BTILE + 27 * BM * 4;  // 224256
    cudaFuncSetAttribute(subm_conv_mma_kernel,
                         cudaFuncAttributeMaxDynamicSharedMemorySize, CONV_SMEM);
    const int HEAD_SMEM = 49152 + 128 * 65 * 4;                 // 82432
    cudaFuncSetAttribute(head_vox_kernel,
                         cudaFuncAttributeMaxDynamicSharedMemorySize, HEAD_SMEM);

    convert_w_kernel<<<1024, 256>>>(conv_w, pwh, 4 * 27 * CCH * CCH);
    convert_w_kernel<<<8, 256>>>(w1, pw1h, CCH * 64);
    cudaMemsetAsync(px, 0, (size_t)M * CCH * sizeof(float));
    cudaMemsetAsync(pcnt, 0, (size_t)M * sizeof(float));
    count_kernel<<<512, 256>>>(inv_idx, pcnt, Np);
    encode_pool_kernel<<<512, 256>>>(gp, w_enc, b_enc, ln_g, ln_b, inv_idx, pcnt, px, Np);
    pool_div_kernel<<<2048, 256>>>(px, pcnt, pxh, M);

    const int tiles = (M + BM - 1) / BM;
    for (int blk = 0; blk < 2; ++blk) {
        const int l0 = 2 * blk, l1 = 2 * blk + 1;
        // conv1 (fused BN stats, fp16 y) -> BN apply -> ReLU (fp16 out)
        cudaMemsetAsync(pstats, 0, 256 * sizeof(float));
        subm_conv_mma_kernel<<<tiles, 512, CONV_SMEM>>>(
            pxh, pwh + (size_t)l0 * 27 * CCH * CCH, nbr_idx, nbr_mask, pyh, pstats, M);
        bn_apply_kernel<<<2048, 256>>>(pyh, bn_g + l0 * CCH, bn_b + l0 * CCH, pstats,
                                       (const __half*)0, pah, M);
        // conv2 (fused BN stats, fp16 y) -> BN apply + fp16 residual (in-place xh)
        cudaMemsetAsync(pstats, 0, 256 * sizeof(float));
        subm_conv_mma_kernel<<<tiles, 512, CONV_SMEM>>>(
            pah, pwh + (size_t)l1 * 27 * CCH * CCH, nbr_idx, nbr_mask, pyh, pstats, M);
        bn_apply_kernel<<<2048, 256>>>(pyh, bn_g + l1 * CCH, bn_b + l1 * CCH, pstats,
                                       pxh, pxh, M);
    }

    head_vox_kernel<<<(M + 127) / 128, 256, HEAD_SMEM>>>(pxh, pw1h, b1, w2, b2, pdv, M);
    scatter_out_kernel<<<1024, 256>>>(gp, pdv, inv_idx, out, Np);
}

// round 16
// speedup vs baseline: 1.5584x; 1.0051x over previous
#include <cuda_runtime.h>
#include <cuda_fp16.h>
#include <stdint.h>
#include <math.h>

#define NPTS 200000
#define CCH  128
#define EPSV 1e-5f
#define ATILE 65536u            // 256 x 128 halfs, swizzled
#define BTILE 32768u            // 128 x 128 halfs, swizzled
#define BM    256
#define YPITCH 136              // halfs per row in epilogue staging (272B)

// ---------------- scratch (device globals; no allocations anywhere) ----------
__device__ float  g_x[NPTS * CCH];           // fp32 pooled sums (encoder)
__device__ float  g_dv[NPTS * 14];           // fp32 dvox (head output)
__device__ __half g_yh[NPTS * CCH];          // fp16 conv output
__device__ __half g_xh[NPTS * CCH];          // fp16 x path (input / residual)
__device__ __half g_ah[NPTS * CCH];          // fp16 mid path
__device__ __half g_wh[4 * 27 * CCH * CCH];  // fp16 conv weights
__device__ __half g_w1h[CCH * 64];           // fp16 head weights
__device__ float  g_cnt[NPTS];
__device__ float  g_stats[256];              // [0..127]=sum [128..255]=sumsq

// ---------------- helpers ----------------
__device__ __forceinline__ unsigned smem_u32(const void* p) {
    return (unsigned)__cvta_generic_to_shared(p);
}
__device__ __forceinline__ unsigned swz(int row, int c16) {
    return (unsigned)(row * 256 + (((c16) ^ (row & 7)) << 4));
}
__device__ __forceinline__ unsigned swz64(int row, int c16) {
    return (unsigned)(row * 128 + (((c16) ^ (row & 7)) << 4));
}
__device__ __forceinline__ void ldsm_x4(uint32_t* r, unsigned addr) {
    asm volatile("ldmatrix.sync.aligned.m8n8.x4.shared.b16 {%0,%1,%2,%3}, [%4];\n"
                 : "=r"(r[0]), "=r"(r[1]), "=r"(r[2]), "=r"(r[3]) : "r"(addr));
}
__device__ __forceinline__ void ldsm_x4_t(uint32_t* r, unsigned addr) {
    asm volatile("ldmatrix.sync.aligned.m8n8.x4.trans.shared.b16 {%0,%1,%2,%3}, [%4];\n"
                 : "=r"(r[0]), "=r"(r[1]), "=r"(r[2]), "=r"(r[3]) : "r"(addr));
}
__device__ __forceinline__ void mma_f16(float* c, const uint32_t* a, uint32_t b0, uint32_t b1) {
    asm volatile("mma.sync.aligned.m16n8k16.row.col.f32.f16.f16.f32 "
                 "{%0,%1,%2,%3}, {%4,%5,%6,%7}, {%8,%9}, {%0,%1,%2,%3};\n"
                 : "+f"(c[0]), "+f"(c[1]), "+f"(c[2]), "+f"(c[3])
                 : "r"(a[0]), "r"(a[1]), "r"(a[2]), "r"(a[3]), "r"(b0), "r"(b1));
}
__device__ __forceinline__ void cp16(unsigned dst, const void* src) {
    asm volatile("cp.async.cg.shared.global [%0], [%1], 16;\n" :: "r"(dst), "l"(src));
}
__device__ __forceinline__ void cp16z(unsigned dst, const void* src, unsigned ssz) {
    asm volatile("cp.async.cg.shared.global [%0], [%1], 16, %2;\n"
                 :: "r"(dst), "l"(src), "r"(ssz));
}

// ---------------- weight fp32 -> fp16 ----------------
__global__ void convert_w_kernel(const float* __restrict__ w, __half* __restrict__ wh, int n) {
    for (int i = blockIdx.x * blockDim.x + threadIdx.x; i < n; i += gridDim.x * blockDim.x)
        wh[i] = __float2half(w[i]);
}

// ---------------- pass 1: per-voxel point counts ------------------------------
__global__ void count_kernel(const int* __restrict__ inv_idx, float* __restrict__ cnt, int Np) {
    for (int i = blockIdx.x * blockDim.x + threadIdx.x; i < Np; i += gridDim.x * blockDim.x)
        atomicAdd(&cnt[inv_idx[i]], 1.f);
}

// ---------------- encoder: warp-per-point, weights in SMEM (low reg pressure) -
__global__ __launch_bounds__(256)
void encode_pool_kernel(const float* __restrict__ gp,
                        const float* __restrict__ w_enc,
                        const float* __restrict__ b_enc,
                        const float* __restrict__ ln_g,
                        const float* __restrict__ ln_b,
                        const int*   __restrict__ inv_idx,
                        const float* __restrict__ cnt,
                        float* __restrict__ xsum,
                        int Np) {
    __shared__ float sw[14][CCH];
    __shared__ float sbe[CCH], slg[CCH], slb[CCH];
    {
        int t = threadIdx.x;
        for (int j = t; j < 14 * CCH; j += 256) sw[j >> 7][j & 127] = w_enc[j];
        if (t < CCH) { sbe[t] = b_enc[t]; slg[t] = ln_g[t]; slb[t] = ln_b[t]; }
    }
    __syncthreads();

    const int lane = threadIdx.x & 31;
    const int gw = (blockIdx.x * blockDim.x + threadIdx.x) >> 5;
    const int nw = (gridDim.x * blockDim.x) >> 5;
    const int c0 = lane * 4;

    const float4 be = *(const float4*)&sbe[c0];
    const float4 lg = *(const float4*)&slg[c0];
    const float4 lb = *(const float4*)&slb[c0];

    for (int i = gw; i < Np; i += nw) {
        float gv = (lane < 14) ? gp[(size_t)i * 14 + lane] : 0.f;
        float f0 = be.x, f1 = be.y, f2 = be.z, f3 = be.w;
#pragma unroll
        for (int k = 0; k < 14; ++k) {
            float s = __shfl_sync(0xffffffffu, gv, k);
            float4 w = *(const float4*)&sw[k][c0];
            f0 += s * w.x; f1 += s * w.y; f2 += s * w.z; f3 += s * w.w;
        }
        float s1 = f0 + f1 + f2 + f3;
        float s2 = f0 * f0 + f1 * f1 + f2 * f2 + f3 * f3;
#pragma unroll
        for (int off = 16; off > 0; off >>= 1) {
            s1 += __shfl_xor_sync(0xffffffffu, s1, off);
            s2 += __shfl_xor_sync(0xffffffffu, s2, off);
        }
        float mu  = s1 * (1.f / 128.f);
        float inv = rsqrtf(s2 * (1.f / 128.f) - mu * mu + EPSV);
        int vox = inv_idx[i];
        float v0 = fmaxf((f0 - mu) * inv * lg.x + lb.x, 0.f);
        float v1 = fmaxf((f1 - mu) * inv * lg.y + lb.y, 0.f);
        float v2 = fmaxf((f2 - mu) * inv * lg.z + lb.z, 0.f);
        float v3 = fmaxf((f3 - mu) * inv * lg.w + lb.w, 0.f);
        float* dst = xsum + (size_t)vox * CCH + c0;
        if (cnt[vox] == 1.f) {
            *(float4*)dst = make_float4(v0, v1, v2, v3);   // sole owner, no race
        } else {
            atomicAdd(dst + 0, v0);
            atomicAdd(dst + 1, v1);
            atomicAdd(dst + 2, v2);
            atomicAdd(dst + 3, v3);
        }
    }
}

// ---------------- pooled sums / counts -> fp16, vectorized --------------------
__global__ void pool_div_kernel(const float* __restrict__ x, const float* __restrict__ cnt,
                                __half* __restrict__ xh, int M) {
    int total4 = M * 32;
    for (int i = blockIdx.x * blockDim.x + threadIdx.x; i < total4; i += gridDim.x * blockDim.x) {
        float inv = 1.f / cnt[i >> 5];
        float4 v = ((const float4*)x)[i];
        ((__half2*)xh)[2 * i]     = __floats2half2_rn(v.x * inv, v.y * inv);
        ((__half2*)xh)[2 * i + 1] = __floats2half2_rn(v.z * inv, v.w * inv);
    }
}

// ---------------- submanifold conv, fp16 mma.sync, cp.async double-buffered ---
__global__ __launch_bounds__(512, 1)
void subm_conv_mma_kernel(const __half* __restrict__ xin,
                          const __half* __restrict__ W,   // 27 x 128 x 128 fp16
                          const int*   __restrict__ nbr_idx,
                          const float* __restrict__ nbr_mask,
                          __half* __restrict__ y,          // fp16 out
                          float* __restrict__ gstats,
                          int M) {
    extern __shared__ __align__(16) char smem_raw[];
    int* sidx = (int*)(smem_raw + 2 * ATILE + 2 * BTILE);   // 27 x 256
    __shared__ unsigned s_fmask[27];
    __shared__ int   s_sal[27], s_nact;
    __shared__ float sstat[CCH], ssq[CCH];

    const int tid  = threadIdx.x;
    const int warp = tid >> 5, lane = tid & 31;
    const int wm = warp >> 1;
    const int wn = warp & 1;
    const int v0 = blockIdx.x * BM;

    for (int j = tid; j < 27 * BM; j += 512) {
        int r = j / 27, o = j - r * 27;
        int v = v0 + r;
        int id = -1;
        if (v < M && nbr_mask[(size_t)v0 * 27 + j] != 0.f)
            id = nbr_idx[(size_t)v0 * 27 + j];
        sidx[o * BM + r] = id;
    }
    if (tid < 27) s_fmask[tid] = 0u;
    if (tid < CCH) { sstat[tid] = 0.f; ssq[tid] = 0.f; }
    __syncthreads();
    if (tid < 432) {
        int o = tid >> 4, f = tid & 15;
        const int* p = sidx + o * BM + f * 16;
        int any = 0;
#pragma unroll
        for (int i = 0; i < 16; ++i) any |= (p[i] >= 0);
        if (any) atomicOr(&s_fmask[o], 1u << f);
    }
    __syncthreads();
    if (tid == 0) {
        int n = 0;
        for (int o = 0; o < 27; ++o) if (s_fmask[o]) s_sal[n++] = o;
        s_nact = n;
    }
    __syncthreads();
    const int nact = s_nact;

    const unsigned sAu = smem_u32(smem_raw);
    const unsigned sBu = sAu + 2 * ATILE;
    const int arow = tid >> 1;
    const int ac0  = (tid & 1) * 8;
    const int afrag = arow >> 4;
    const int brow = tid >> 2;
    const int bc0  = (tid & 3) * 4;

    float acc[2][8][4];
#pragma unroll
    for (int mi = 0; mi < 2; ++mi)
#pragma unroll
        for (int ni = 0; ni < 8; ++ni)
#pragma unroll
            for (int q = 0; q < 4; ++q) acc[mi][ni][q] = 0.f;

    {   // stage offset 0 into buffer 0
        int o = s_sal[0];
        if ((s_fmask[o] >> afrag) & 1u) {
            int id = sidx[o * BM + arow];
            unsigned ssz = (id >= 0) ? 16u : 0u;
            const __half* srcA = xin + (size_t)(id >= 0 ? id : 0) * CCH + ac0 * 8;
#pragma unroll
            for (int q = 0; q < 8; ++q)
                cp16z(sAu + swz(arow, ac0 + q), srcA + q * 8, ssz);
        }
        const __half* srcB = W + (size_t)o * CCH * CCH + brow * CCH + bc0 * 8;
#pragma unroll
        for (int q = 0; q < 4; ++q)
            cp16 (sBu + swz(brow, bc0 + q), srcB + q * 8);
        asm volatile("cp.async.commit_group;\n" ::: "memory");
    }

    for (int t = 0; t < nact; ++t) {
        const int b = t & 1;
        const unsigned fmask = s_fmask[s_sal[t]];
        const bool act0 = (fmask >> (2 * wm)) & 1u;
        const bool act1 = (fmask >> (2 * wm + 1)) & 1u;

        asm volatile("cp.async.wait_group 0;\n" ::: "memory");
        __syncthreads();
        if (t + 1 < nact) {
            int o = s_sal[t + 1];
            unsigned dA = sAu + (unsigned)((b ^ 1) * ATILE);
            unsigned dB = sBu + (unsigned)((b ^ 1) * BTILE);
            if ((s_fmask[o] >> afrag) & 1u) {
                int id = sidx[o * BM + arow];
                unsigned ssz = (id >= 0) ? 16u : 0u;
                const __half* srcA = xin + (size_t)(id >= 0 ? id : 0) * CCH + ac0 * 8;
#pragma unroll
                for (int q = 0; q < 8; ++q)
                    cp16z(dA + swz(arow, ac0 + q), srcA + q * 8, ssz);
            }
            const __half* srcB = W + (size_t)o * CCH * CCH + brow * CCH + bc0 * 8;
#pragma unroll
            for (int q = 0; q < 4; ++q)
                cp16 (dB + swz(brow, bc0 + q), srcB + q * 8);
            asm volatile("cp.async.commit_group;\n" ::: "memory");
        }

        if (act0 | act1) {
            const unsigned Ab = sAu + (unsigned)(b * ATILE);
            const unsigned Bb = sBu + (unsigned)(b * BTILE);
#pragma unroll
            for (int kc = 0; kc < 8; ++kc) {
                uint32_t a[2][4];
                if (act0) {
                    int row = wm * 32 + (lane & 15);
                    ldsm_x4(a[0], Ab + swz(row, kc * 2 + (lane >> 4)));
                }
                if (act1) {
                    int row = wm * 32 + 16 + (lane & 15);
                    ldsm_x4(a[1], Ab + swz(row, kc * 2 + (lane >> 4)));
                }
#pragma unroll
                for (int nb = 0; nb < 4; ++nb) {
                    uint32_t bb[4];
                    int row = kc * 16 + (lane & 15);
                    ldsm_x4_t(bb, Bb + swz(row, wn * 8 + nb * 2 + (lane >> 4)));
                    if (act0) {
                        mma_f16(acc[0][nb * 2 + 0], a[0], bb[0], bb[1]);
                        mma_f16(acc[0][nb * 2 + 1], a[0], bb[2], bb[3]);
                    }
                    if (act1) {
                        mma_f16(acc[1][nb * 2 + 0], a[1], bb[0], bb[1]);
                        mma_f16(acc[1][nb * 2 + 1], a[1], bb[2], bb[3]);
                    }
                }
            }
        }
        __syncthreads();
    }

    // ---- BN partials (fp32, pre-quantization) --------------------------------
    const int cbase = wn * 64 + (lane & 3) * 2;
#pragma unroll
    for (int ni = 0; ni < 8; ++ni) {
#pragma unroll
        for (int tt = 0; tt < 2; ++tt) {
            float a0 = acc[0][ni][tt],     a1 = acc[0][ni][2 + tt];
            float a2 = acc[1][ni][tt],     a3 = acc[1][ni][2 + tt];
            float s = a0 + a1 + a2 + a3;
            float q = a0 * a0 + a1 * a1 + a2 * a2 + a3 * a3;
#pragma unroll
            for (int off = 4; off <= 16; off <<= 1) {
                s += __shfl_xor_sync(0xffffffffu, s, off);
                q += __shfl_xor_sync(0xffffffffu, q, off);
            }
            if ((lane >> 2) == 0) {
                int c = cbase + ni * 8 + tt;
                atomicAdd(&sstat[c], s);
                atomicAdd(&ssq[c], q);
            }
        }
    }

    // ---- epilogue: stage fp16 tile in smem, then coalesced full-sector copy --
    __half* ytile = (__half*)smem_raw;   // 256 x 136 halfs
    const int rrel = wm * 32 + (lane >> 2);
#pragma unroll
    for (int mi = 0; mi < 2; ++mi) {
#pragma unroll
        for (int ni = 0; ni < 8; ++ni) {
            int col = cbase + ni * 8;
            int r0 = rrel + mi * 16;
            *(__half2*)(ytile + r0 * YPITCH + col) =
                __floats2half2_rn(acc[mi][ni][0], acc[mi][ni][1]);
            *(__half2*)(ytile + (r0 + 8) * YPITCH + col) =
                __floats2half2_rn(acc[mi][ni][2], acc[mi][ni][3]);
        }
    }
    __syncthreads();
    for (int ch = tid; ch < 4096; ch += 512) {
        int row = ch >> 4, c16 = ch & 15;
        int gv = v0 + row;
        if (gv < M) {
            uint4 val = *(const uint4*)(ytile + row * YPITCH + c16 * 8);
            *(uint4*)(y + (size_t)gv * CCH + c16 * 8) = val;
        }
    }
    if (tid < CCH) {
        atomicAdd(&gstats[tid],       sstat[tid]);
        atomicAdd(&gstats[CCH + tid], ssq[tid]);
    }
}

// ---------------- BN apply: hoisted scale/bias, uint4 fp16 in/out -------------
__global__ __launch_bounds__(256)
void bn_apply_kernel(const __half* __restrict__ y,
                     const float* __restrict__ g,
                     const float* __restrict__ b,
                     const float* __restrict__ stats,
                     const __half* __restrict__ residual,   // nullable (fp16)
                     __half* __restrict__ out_h16,
                     int M) {
    __shared__ float sc[CCH], sb[CCH];
    float invM = 1.f / (float)M;
    if (threadIdx.x < CCH) {
        int c = threadIdx.x;
        float m   = stats[c] * invM;
        float var = stats[128 + c] * invM - m * m;
        float s = rsqrtf(var + EPSV) * g[c];
        sc[c] = s;
        sb[c] = b[c] - m * s;
    }
    __syncthreads();

    int total8 = M * 16;
    for (int i = blockIdx.x * blockDim.x + threadIdx.x; i < total8; i += gridDim.x * blockDim.x) {
        int c0 = (i & 15) * 8;
        uint4 yv = ((const uint4*)y)[i];
        float2 p0 = __half22float2(*(__half2*)&yv.x);
        float2 p1 = __half22float2(*(__half2*)&yv.y);
        float2 p2 = __half22float2(*(__half2*)&yv.z);
        float2 p3 = __half22float2(*(__half2*)&yv.w);
        float v[8] = {p0.x, p0.y, p1.x, p1.y, p2.x, p2.y, p3.x, p3.y};
#pragma unroll
        for (int q = 0; q < 8; ++q) v[q] = v[q] * sc[c0 + q] + sb[c0 + q];
        if (residual) {
            uint4 rv = ((const uint4*)residual)[i];
            float2 r0 = __half22float2(*(__half2*)&rv.x);
            float2 r1 = __half22float2(*(__half2*)&rv.y);
            float2 r2 = __half22float2(*(__half2*)&rv.z);
            float2 r3 = __half22float2(*(__half2*)&rv.w);
            v[0] += r0.x; v[1] += r0.y; v[2] += r1.x; v[3] += r1.y;
            v[4] += r2.x; v[5] += r2.y; v[6] += r3.x; v[7] += r3.y;
        }
#pragma unroll
        for (int q = 0; q < 8; ++q) v[q] = fmaxf(v[q], 0.f);
        uint4 ov;
        *(__half2*)&ov.x = __floats2half2_rn(v[0], v[1]);
        *(__half2*)&ov.y = __floats2half2_rn(v[2], v[3]);
        *(__half2*)&ov.z = __floats2half2_rn(v[4], v[5]);
        *(__half2*)&ov.w = __floats2half2_rn(v[6], v[7]);
        ((uint4*)out_h16)[i] = ov;
    }
}

// ---------------- head on voxels: dvox = relu(x@w1+b1)@w2 + b2 ----------------
__global__ __launch_bounds__(256)
void head_vox_kernel(const __half* __restrict__ xh,
                     const __half* __restrict__ w1h,
                     const float* __restrict__ b1,
                     const float* __restrict__ w2,
                     const float* __restrict__ b2,
                     float* __restrict__ dvox,
                     int M) {
    extern __shared__ __align__(16) char smem_raw[];
    float* hs = (float*)(smem_raw + 49152);
    __shared__ float b1s[64], b2s[14], w2s[64 * 14];

    const int tid  = threadIdx.x;
    const int warp = tid >> 5, lane = tid & 31;
    const int v0 = blockIdx.x * 128;

    const unsigned sAu = smem_u32(smem_raw);
    const unsigned sBu = sAu + 32768u;

    {
        int row = tid >> 1, c0 = (tid & 1) * 8;
        unsigned ssz = (v0 + row < M) ? 16u : 0u;
        const __half* srcA = xh + (size_t)(v0 + row < M ? v0 + row : 0) * CCH + c0 * 8;
#pragma unroll
        for (int q = 0; q < 8; ++q)
            cp16z(sAu + swz(row, c0 + q), srcA + q * 8, ssz);
    }
    for (int j = tid; j < 1024; j += 256) {
        int row = j >> 3, c = j & 7;
        cp16(sBu + swz64(row, c), w1h + row * 64 + c * 8);
    }
    asm volatile("cp.async.commit_group;\n" ::: "memory");
    if (tid < 64) b1s[tid] = b1[tid];
    if (tid < 14) b2s[tid] = b2[tid];
    for (int j = tid; j < 64 * 14; j += 256) w2s[j] = w2[j];
    asm volatile("cp.async.wait_group 0;\n" ::: "memory");
    __syncthreads();

    float acc[8][4];
#pragma unroll
    for (int ni = 0; ni < 8; ++ni)
#pragma unroll
        for (int q = 0; q < 4; ++q) acc[ni][q] = 0.f;
#pragma unroll
    for (int kc = 0; kc < 8; ++kc) {
        uint32_t a[4];
        ldsm_x4(a, sAu + swz(warp * 16 + (lane & 15), kc * 2 + (lane >> 4)));
#pragma unroll
        for (int nb = 0; nb < 4; ++nb) {
            uint32_t bb[4];
            ldsm_x4_t(bb, sBu + swz64(kc * 16 + (lane & 15), nb * 2 + (lane >> 4)));
            mma_f16(acc[nb * 2 + 0], a, bb[0], bb[1]);
            mma_f16(acc[nb * 2 + 1], a, bb[2], bb[3]);
        }
    }
    {
        int r0 = warp * 16 + (lane >> 2);
        int c0 = (lane & 3) * 2;
#pragma unroll
        for (int ni = 0; ni < 8; ++ni) {
            int c = c0 + ni * 8;
            hs[r0 * 65 + c]           = fmaxf(acc[ni][0] + b1s[c], 0.f);
            hs[r0 * 65 + c + 1]       = fmaxf(acc[ni][1] + b1s[c + 1], 0.f);
            hs[(r0 + 8) * 65 + c]     = fmaxf(acc[ni][2] + b1s[c], 0.f);
            hs[(r0 + 8) * 65 + c + 1] = fmaxf(acc[ni][3] + b1s[c + 1], 0.f);
        }
    }
    __syncthreads();

    {
        int r = tid >> 1;
        int cb = (tid & 1) * 7;
        if (v0 + r < M) {
            float d[7];
#pragma unroll
            for (int c = 0; c < 7; ++c) d[c] = b2s[cb + c];
#pragma unroll 8
            for (int k = 0; k < 64; ++k) {
                float hv = hs[r * 65 + k];
#pragma unroll
                for (int c = 0; c < 7; ++c) d[c] += hv * w2s[k * 14 + cb + c];
            }
            float* dst = dvox + (size_t)(v0 + r) * 14 + cb;
#pragma unroll
            for (int c = 0; c < 7; ++c) dst[c] = d[c];
        }
    }
}

// ---------------- scatter: out = gp + dvox[inv_idx], thread-per-point ---------
__global__ void scatter_out_kernel(const float* __restrict__ gp,
                                   const float* __restrict__ dvox,
                                   const int*   __restrict__ inv_idx,
                                   float* __restrict__ out, int Np) {
    for (int i = blockIdx.x * blockDim.x + threadIdx.x; i < Np; i += gridDim.x * blockDim.x) {
        const float* dr = dvox + (size_t)inv_idx[i] * 14;
        const float* gr = gp + (size_t)i * 14;
        float* orow = out + (size_t)i * 14;
#pragma unroll
        for (int j = 0; j < 14; ++j) orow[j] = gr[j] + dr[j];
    }
}

// ---------------- launch -------------------------------------------------------
extern "C" void kernel_launch(void* const* d_in, const int* in_sizes, int n_in,
                              void* d_out, int out_size) {
    const float* gp       = (const float*)d_in[0];
    const float* w_enc    = (const float*)d_in[1];
    const float* b_enc    = (const float*)d_in[2];
    const float* ln_g     = (const float*)d_in[3];
    const float* ln_b     = (const float*)d_in[4];
    const float* conv_w   = (const float*)d_in[5];
    const float* bn_g     = (const float*)d_in[6];
    const float* bn_b     = (const float*)d_in[7];
    const float* w1       = (const float*)d_in[8];
    const float* b1       = (const float*)d_in[9];
    const float* w2       = (const float*)d_in[10];
    const float* b2       = (const float*)d_in[11];
    const float* nbr_mask = (const float*)d_in[12];
    const int*   inv_idx  = (const int*)d_in[13];
    const int*   nbr_idx  = (const int*)d_in[14];
    float* out = (float*)d_out;

    const int Np = in_sizes[0] / 14;
    const int M  = in_sizes[12] / 27;

    float *px, *pdv, *pcnt, *pstats;
    __half *pyh, *pxh, *pah, *pwh, *pw1h;
    cudaGetSymbolAddress((void**)&px,     g_x);
    cudaGetSymbolAddress((void**)&pdv,    g_dv);
    cudaGetSymbolAddress((void**)&pyh,    g_yh);
    cudaGetSymbolAddress((void**)&pxh,    g_xh);
    cudaGetSymbolAddress((void**)&pah,    g_ah);
    cudaGetSymbolAddress((void**)&pwh,    g_wh);
    cudaGetSymbolAddress((void**)&pw1h,   g_w1h);
    cudaGetSymbolAddress((void**)&pcnt,   g_cnt);
    cudaGetSymbolAddress((void**)&pstats, g_stats);

    const int CONV_SMEM = 2 * ATILE + 2 * BTILE + 27 * BM * 4;  // 224256
    cudaFuncSetAttribute(subm_conv_mma_kernel,
                         cudaFuncAttributeMaxDynamicSharedMemorySize, CONV_SMEM);
    const int HEAD_SMEM = 49152 + 128 * 65 * 4;                 // 82432
    cudaFuncSetAttribute(head_vox_kernel,
                         cudaFuncAttributeMaxDynamicSharedMemorySize, HEAD_SMEM);

    convert_w_kernel<<<1024, 256>>>(conv_w, pwh, 4 * 27 * CCH * CCH);
    convert_w_kernel<<<8, 256>>>(w1, pw1h, CCH * 64);
    cudaMemsetAsync(px, 0, (size_t)M * CCH * sizeof(float));
    cudaMemsetAsync(pcnt, 0, (size_t)M * sizeof(float));
    count_kernel<<<512, 256>>>(inv_idx, pcnt, Np);
    encode_pool_kernel<<<1024, 256>>>(gp, w_enc, b_enc, ln_g, ln_b, inv_idx, pcnt, px, Np);
    pool_div_kernel<<<2048, 256>>>(px, pcnt, pxh, M);

    const int tiles = (M + BM - 1) / BM;
    for (int blk = 0; blk < 2; ++blk) {
        const int l0 = 2 * blk, l1 = 2 * blk + 1;
        // conv1 (fused BN stats, fp16 y) -> BN apply -> ReLU (fp16 out)
        cudaMemsetAsync(pstats, 0, 256 * sizeof(float));
        subm_conv_mma_kernel<<<tiles, 512, CONV_SMEM>>>(
            pxh, pwh + (size_t)l0 * 27 * CCH * CCH, nbr_idx, nbr_mask, pyh, pstats, M);
        bn_apply_kernel<<<2048, 256>>>(pyh, bn_g + l0 * CCH, bn_b + l0 * CCH, pstats,
                                       (const __half*)0, pah, M);
        // conv2 (fused BN stats, fp16 y) -> BN apply + fp16 residual (in-place xh)
        cudaMemsetAsync(pstats, 0, 256 * sizeof(float));
        subm_conv_mma_kernel<<<tiles, 512, CONV_SMEM>>>(
            pah, pwh + (size_t)l1 * 27 * CCH * CCH, nbr_idx, nbr_mask, pyh, pstats, M);
        bn_apply_kernel<<<2048, 256>>>(pyh, bn_g + l1 * CCH, bn_b + l1 * CCH, pstats,
                                       pxh, pxh, M);
    }

    head_vox_kernel<<<(M + 127) / 128, 256, HEAD_SMEM>>>(pxh, pw1h, b1, w2, b2, pdv, M);
    scatter_out_kernel<<<1024, 256>>>(gp, pdv, inv_idx, out, Np);
}

// round 17
// speedup vs baseline: 1.5747x; 1.0105x over previous
#include <cuda_runtime.h>
#include <cuda_fp16.h>
#include <stdint.h>
#include <math.h>

#define NPTS 200000
#define CCH  128
#define EPSV 1e-5f
#define ATILE 65536u            // 256 x 128 halfs, swizzled
#define BTILE 32768u            // 128 x 128 halfs, swizzled
#define BM    256
#define YPITCH 136              // halfs per row in epilogue staging (272B)

// ---------------- scratch (device globals; no allocations anywhere) ----------
__device__ float  g_x[NPTS * CCH];           // fp32 pooled sums (encoder)
__device__ float  g_dv[NPTS * 14];           // fp32 dvox (head output)
__device__ __half g_yh[NPTS * CCH];          // fp16 conv output
__device__ __half g_xh[NPTS * CCH];          // fp16 x path (input / residual)
__device__ __half g_ah[NPTS * CCH];          // fp16 mid path
__device__ __half g_wh[4 * 27 * CCH * CCH];  // fp16 conv weights
__device__ __half g_w1h[CCH * 64];           // fp16 head weights
__device__ float  g_cnt[NPTS];
__device__ float  g_stats[256];              // [0..127]=sum [128..255]=sumsq

// ---------------- helpers ----------------
__device__ __forceinline__ unsigned smem_u32(const void* p) {
    return (unsigned)__cvta_generic_to_shared(p);
}
__device__ __forceinline__ unsigned swz(int row, int c16) {
    return (unsigned)(row * 256 + (((c16) ^ (row & 7)) << 4));
}
__device__ __forceinline__ unsigned swz64(int row, int c16) {
    return (unsigned)(row * 128 + (((c16) ^ (row & 7)) << 4));
}
__device__ __forceinline__ void ldsm_x4(uint32_t* r, unsigned addr) {
    asm volatile("ldmatrix.sync.aligned.m8n8.x4.shared.b16 {%0,%1,%2,%3}, [%4];\n"
                 : "=r"(r[0]), "=r"(r[1]), "=r"(r[2]), "=r"(r[3]) : "r"(addr));
}
__device__ __forceinline__ void ldsm_x4_t(uint32_t* r, unsigned addr) {
    asm volatile("ldmatrix.sync.aligned.m8n8.x4.trans.shared.b16 {%0,%1,%2,%3}, [%4];\n"
                 : "=r"(r[0]), "=r"(r[1]), "=r"(r[2]), "=r"(r[3]) : "r"(addr));
}
__device__ __forceinline__ void mma_f16(float* c, const uint32_t* a, uint32_t b0, uint32_t b1) {
    asm volatile("mma.sync.aligned.m16n8k16.row.col.f32.f16.f16.f32 "
                 "{%0,%1,%2,%3}, {%4,%5,%6,%7}, {%8,%9}, {%0,%1,%2,%3};\n"
                 : "+f"(c[0]), "+f"(c[1]), "+f"(c[2]), "+f"(c[3])
                 : "r"(a[0]), "r"(a[1]), "r"(a[2]), "r"(a[3]), "r"(b0), "r"(b1));
}
__device__ __forceinline__ void cp16(unsigned dst, const void* src) {
    asm volatile("cp.async.cg.shared.global [%0], [%1], 16;\n" :: "r"(dst), "l"(src));
}
__device__ __forceinline__ void cp16z(unsigned dst, const void* src, unsigned ssz) {
    asm volatile("cp.async.cg.shared.global [%0], [%1], 16, %2;\n"
                 :: "r"(dst), "l"(src), "r"(ssz));
}

// ---------------- weight fp32 -> fp16 ----------------
__global__ void convert_w_kernel(const float* __restrict__ w, __half* __restrict__ wh, int n) {
    for (int i = blockIdx.x * blockDim.x + threadIdx.x; i < n; i += gridDim.x * blockDim.x)
        wh[i] = __float2half(w[i]);
}

// ---------------- pass 1: per-voxel point counts ------------------------------
__global__ void count_kernel(const int* __restrict__ inv_idx, float* __restrict__ cnt, int Np) {
    for (int i = blockIdx.x * blockDim.x + threadIdx.x; i < Np; i += gridDim.x * blockDim.x)
        atomicAdd(&cnt[inv_idx[i]], 1.f);
}

// ---------------- encoder: 2 points per warp iteration (ILP), SMEM weights ----
__global__ __launch_bounds__(256)
void encode_pool_kernel(const float* __restrict__ gp,
                        const float* __restrict__ w_enc,
                        const float* __restrict__ b_enc,
                        const float* __restrict__ ln_g,
                        const float* __restrict__ ln_b,
                        const int*   __restrict__ inv_idx,
                        const float* __restrict__ cnt,
                        float* __restrict__ xsum,
                        int Np) {
    __shared__ float sw[14][CCH];
    __shared__ float sbe[CCH], slg[CCH], slb[CCH];
    {
        int t = threadIdx.x;
        for (int j = t; j < 14 * CCH; j += 256) sw[j >> 7][j & 127] = w_enc[j];
        if (t < CCH) { sbe[t] = b_enc[t]; slg[t] = ln_g[t]; slb[t] = ln_b[t]; }
    }
    __syncthreads();

    const int lane = threadIdx.x & 31;
    const int gw = (blockIdx.x * blockDim.x + threadIdx.x) >> 5;
    const int nw = (gridDim.x * blockDim.x) >> 5;
    const int c0 = lane * 4;

    const float4 be = *(const float4*)&sbe[c0];
    const float4 lg = *(const float4*)&slg[c0];
    const float4 lb = *(const float4*)&slb[c0];

    for (int i = gw * 2; i < Np; i += nw * 2) {
        const int ia = i, ib = i + 1;
        const bool okb = (ib < Np);
        // lanes 0-13 hold point A inputs, lanes 16-29 hold point B inputs
        float gv = 0.f;
        if (lane < 14) gv = gp[(size_t)ia * 14 + lane];
        else if (lane >= 16 && lane < 30 && okb) gv = gp[(size_t)ib * 14 + (lane - 16)];

        float a0 = be.x, a1 = be.y, a2 = be.z, a3 = be.w;
        float b0 = be.x, b1 = be.y, b2 = be.z, b3 = be.w;
#pragma unroll
        for (int k = 0; k < 14; ++k) {
            float sa = __shfl_sync(0xffffffffu, gv, k);
            float sb2 = __shfl_sync(0xffffffffu, gv, 16 + k);
            float4 w = *(const float4*)&sw[k][c0];
            a0 += sa * w.x; a1 += sa * w.y; a2 += sa * w.z; a3 += sa * w.w;
            b0 += sb2 * w.x; b1 += sb2 * w.y; b2 += sb2 * w.z; b3 += sb2 * w.w;
        }
        float s1a = a0 + a1 + a2 + a3;
        float s2a = a0 * a0 + a1 * a1 + a2 * a2 + a3 * a3;
        float s1b = b0 + b1 + b2 + b3;
        float s2b = b0 * b0 + b1 * b1 + b2 * b2 + b3 * b3;
#pragma unroll
        for (int off = 16; off > 0; off >>= 1) {
            s1a += __shfl_xor_sync(0xffffffffu, s1a, off);
            s2a += __shfl_xor_sync(0xffffffffu, s2a, off);
            s1b += __shfl_xor_sync(0xffffffffu, s1b, off);
            s2b += __shfl_xor_sync(0xffffffffu, s2b, off);
        }
        {
            float mu  = s1a * (1.f / 128.f);
            float inv = rsqrtf(s2a * (1.f / 128.f) - mu * mu + EPSV);
            int vox = inv_idx[ia];
            float v0 = fmaxf((a0 - mu) * inv * lg.x + lb.x, 0.f);
            float v1 = fmaxf((a1 - mu) * inv * lg.y + lb.y, 0.f);
            float v2 = fmaxf((a2 - mu) * inv * lg.z + lb.z, 0.f);
            float v3 = fmaxf((a3 - mu) * inv * lg.w + lb.w, 0.f);
            float* dst = xsum + (size_t)vox * CCH + c0;
            if (cnt[vox] == 1.f) {
                *(float4*)dst = make_float4(v0, v1, v2, v3);
            } else {
                atomicAdd(dst + 0, v0);
                atomicAdd(dst + 1, v1);
                atomicAdd(dst + 2, v2);
                atomicAdd(dst + 3, v3);
            }
        }
        if (okb) {
            float mu  = s1b * (1.f / 128.f);
            float inv = rsqrtf(s2b * (1.f / 128.f) - mu * mu + EPSV);
            int vox = inv_idx[ib];
            float v0 = fmaxf((b0 - mu) * inv * lg.x + lb.x, 0.f);
            float v1 = fmaxf((b1 - mu) * inv * lg.y + lb.y, 0.f);
            float v2 = fmaxf((b2 - mu) * inv * lg.z + lb.z, 0.f);
            float v3 = fmaxf((b3 - mu) * inv * lg.w + lb.w, 0.f);
            float* dst = xsum + (size_t)vox * CCH + c0;
            if (cnt[vox] == 1.f) {
                *(float4*)dst = make_float4(v0, v1, v2, v3);
            } else {
                atomicAdd(dst + 0, v0);
                atomicAdd(dst + 1, v1);
                atomicAdd(dst + 2, v2);
                atomicAdd(dst + 3, v3);
            }
        }
    }
}

// ---------------- pooled sums / counts -> fp16, vectorized --------------------
__global__ void pool_div_kernel(const float* __restrict__ x, const float* __restrict__ cnt,
                                __half* __restrict__ xh, int M) {
    int total4 = M * 32;
    for (int i = blockIdx.x * blockDim.x + threadIdx.x; i < total4; i += gridDim.x * blockDim.x) {
        float inv = 1.f / cnt[i >> 5];
        float4 v = ((const float4*)x)[i];
        ((__half2*)xh)[2 * i]     = __floats2half2_rn(v.x * inv, v.y * inv);
        ((__half2*)xh)[2 * i + 1] = __floats2half2_rn(v.z * inv, v.w * inv);
    }
}

// ---------------- submanifold conv, fp16 mma.sync, cp.async double-buffered ---
__global__ __launch_bounds__(512, 1)
void subm_conv_mma_kernel(const __half* __restrict__ xin,
                          const __half* __restrict__ W,   // 27 x 128 x 128 fp16
                          const int*   __restrict__ nbr_idx,
                          const float* __restrict__ nbr_mask,
                          __half* __restrict__ y,          // fp16 out
                          float* __restrict__ gstats,
                          int M) {
    extern __shared__ __align__(16) char smem_raw[];
    int* sidx = (int*)(smem_raw + 2 * ATILE + 2 * BTILE);   // 27 x 256
    __shared__ unsigned s_fmask[27];
    __shared__ int   s_sal[27], s_nact;
    __shared__ float sstat[CCH], ssq[CCH];

    const int tid  = threadIdx.x;
    const int warp = tid >> 5, lane = tid & 31;
    const int wm = warp >> 1;
    const int wn = warp & 1;
    const int v0 = blockIdx.x * BM;

    for (int j = tid; j < 27 * BM; j += 512) {
        int r = j / 27, o = j - r * 27;
        int v = v0 + r;
        int id = -1;
        if (v < M && nbr_mask[(size_t)v0 * 27 + j] != 0.f)
            id = nbr_idx[(size_t)v0 * 27 + j];
        sidx[o * BM + r] = id;
    }
    if (tid < 27) s_fmask[tid] = 0u;
    if (tid < CCH) { sstat[tid] = 0.f; ssq[tid] = 0.f; }
    __syncthreads();
    if (tid < 432) {
        int o = tid >> 4, f = tid & 15;
        const int* p = sidx + o * BM + f * 16;
        int any = 0;
#pragma unroll
        for (int i = 0; i < 16; ++i) any |= (p[i] >= 0);
        if (any) atomicOr(&s_fmask[o], 1u << f);
    }
    __syncthreads();
    if (tid == 0) {
        int n = 0;
        for (int o = 0; o < 27; ++o) if (s_fmask[o]) s_sal[n++] = o;
        s_nact = n;
    }
    __syncthreads();
    const int nact = s_nact;

    const unsigned sAu = smem_u32(smem_raw);
    const unsigned sBu = sAu + 2 * ATILE;
    const int arow = tid >> 1;
    const int ac0  = (tid & 1) * 8;
    const int afrag = arow >> 4;
    const int brow = tid >> 2;
    const int bc0  = (tid & 3) * 4;

    float acc[2][8][4];
#pragma unroll
    for (int mi = 0; mi < 2; ++mi)
#pragma unroll
        for (int ni = 0; ni < 8; ++ni)
#pragma unroll
            for (int q = 0; q < 4; ++q) acc[mi][ni][q] = 0.f;

    {   // stage offset 0 into buffer 0
        int o = s_sal[0];
        if ((s_fmask[o] >> afrag) & 1u) {
            int id = sidx[o * BM + arow];
            unsigned ssz = (id >= 0) ? 16u : 0u;
            const __half* srcA = xin + (size_t)(id >= 0 ? id : 0) * CCH + ac0 * 8;
#pragma unroll
            for (int q = 0; q < 8; ++q)
                cp16z(sAu + swz(arow, ac0 + q), srcA + q * 8, ssz);
        }
        const __half* srcB = W + (size_t)o * CCH * CCH + brow * CCH + bc0 * 8;
#pragma unroll
        for (int q = 0; q < 4; ++q)
            cp16 (sBu + swz(brow, bc0 + q), srcB + q * 8);
        asm volatile("cp.async.commit_group;\n" ::: "memory");
    }

    for (int t = 0; t < nact; ++t) {
        const int b = t & 1;
        const unsigned fmask = s_fmask[s_sal[t]];
        const bool act0 = (fmask >> (2 * wm)) & 1u;
        const bool act1 = (fmask >> (2 * wm + 1)) & 1u;

        asm volatile("cp.async.wait_group 0;\n" ::: "memory");
        __syncthreads();
        if (t + 1 < nact) {
            int o = s_sal[t + 1];
            unsigned dA = sAu + (unsigned)((b ^ 1) * ATILE);
            unsigned dB = sBu + (unsigned)((b ^ 1) * BTILE);
            if ((s_fmask[o] >> afrag) & 1u) {
                int id = sidx[o * BM + arow];
                unsigned ssz = (id >= 0) ? 16u : 0u;
                const __half* srcA = xin + (size_t)(id >= 0 ? id : 0) * CCH + ac0 * 8;
#pragma unroll
                for (int q = 0; q < 8; ++q)
                    cp16z(dA + swz(arow, ac0 + q), srcA + q * 8, ssz);
            }
            const __half* srcB = W + (size_t)o * CCH * CCH + brow * CCH + bc0 * 8;
#pragma unroll
            for (int q = 0; q < 4; ++q)
                cp16 (dB + swz(brow, bc0 + q), srcB + q * 8);
            asm volatile("cp.async.commit_group;\n" ::: "memory");
        }

        if (act0 | act1) {
            const unsigned Ab = sAu + (unsigned)(b * ATILE);
            const unsigned Bb = sBu + (unsigned)(b * BTILE);
#pragma unroll
            for (int kc = 0; kc < 8; ++kc) {
                uint32_t a[2][4];
                if (act0) {
                    int row = wm * 32 + (lane & 15);
                    ldsm_x4(a[0], Ab + swz(row, kc * 2 + (lane >> 4)));
                }
                if (act1) {
                    int row = wm * 32 + 16 + (lane & 15);
                    ldsm_x4(a[1], Ab + swz(row, kc * 2 + (lane >> 4)));
                }
#pragma unroll
                for (int nb = 0; nb < 4; ++nb) {
                    uint32_t bb[4];
                    int row = kc * 16 + (lane & 15);
                    ldsm_x4_t(bb, Bb + swz(row, wn * 8 + nb * 2 + (lane >> 4)));
                    if (act0) {
                        mma_f16(acc[0][nb * 2 + 0], a[0], bb[0], bb[1]);
                        mma_f16(acc[0][nb * 2 + 1], a[0], bb[2], bb[3]);
                    }
                    if (act1) {
                        mma_f16(acc[1][nb * 2 + 0], a[1], bb[0], bb[1]);
                        mma_f16(acc[1][nb * 2 + 1], a[1], bb[2], bb[3]);
                    }
                }
            }
        }
        __syncthreads();
    }

    // ---- BN partials (fp32, pre-quantization) --------------------------------
    const int cbase = wn * 64 + (lane & 3) * 2;
#pragma unroll
    for (int ni = 0; ni < 8; ++ni) {
#pragma unroll
        for (int tt = 0; tt < 2; ++tt) {
            float a0 = acc[0][ni][tt],     a1 = acc[0][ni][2 + tt];
            float a2 = acc[1][ni][tt],     a3 = acc[1][ni][2 + tt];
            float s = a0 + a1 + a2 + a3;
            float q = a0 * a0 + a1 * a1 + a2 * a2 + a3 * a3;
#pragma unroll
            for (int off = 4; off <= 16; off <<= 1) {
                s += __shfl_xor_sync(0xffffffffu, s, off);
                q += __shfl_xor_sync(0xffffffffu, q, off);
            }
            if ((lane >> 2) == 0) {
                int c = cbase + ni * 8 + tt;
                atomicAdd(&sstat[c], s);
                atomicAdd(&ssq[c], q);
            }
        }
    }

    // ---- epilogue: stage fp16 tile in smem, then coalesced full-sector copy --
    __half* ytile = (__half*)smem_raw;   // 256 x 136 halfs
    const int rrel = wm * 32 + (lane >> 2);
#pragma unroll
    for (int mi = 0; mi < 2; ++mi) {
#pragma unroll
        for (int ni = 0; ni < 8; ++ni) {
            int col = cbase + ni * 8;
            int r0 = rrel + mi * 16;
            *(__half2*)(ytile + r0 * YPITCH + col) =
                __floats2half2_rn(acc[mi][ni][0], acc[mi][ni][1]);
            *(__half2*)(ytile + (r0 + 8) * YPITCH + col) =
                __floats2half2_rn(acc[mi][ni][2], acc[mi][ni][3]);
        }
    }
    __syncthreads();
    for (int ch = tid; ch < 4096; ch += 512) {
        int row = ch >> 4, c16 = ch & 15;
        int gv = v0 + row;
        if (gv < M) {
            uint4 val = *(const uint4*)(ytile + row * YPITCH + c16 * 8);
            *(uint4*)(y + (size_t)gv * CCH + c16 * 8) = val;
        }
    }
    if (tid < CCH) {
        atomicAdd(&gstats[tid],       sstat[tid]);
        atomicAdd(&gstats[CCH + tid], ssq[tid]);
    }
}

// ---------------- BN apply: hoisted scale/bias, uint4 fp16 in/out -------------
__global__ __launch_bounds__(256)
void bn_apply_kernel(const __half* __restrict__ y,
                     const float* __restrict__ g,
                     const float* __restrict__ b,
                     const float* __restrict__ stats,
                     const __half* __restrict__ residual,   // nullable (fp16)
                     __half* __restrict__ out_h16,
                     int M) {
    __shared__ float sc[CCH], sb[CCH];
    float invM = 1.f / (float)M;
    if (threadIdx.x < CCH) {
        int c = threadIdx.x;
        float m   = stats[c] * invM;
        float var = stats[128 + c] * invM - m * m;
        float s = rsqrtf(var + EPSV) * g[c];
        sc[c] = s;
        sb[c] = b[c] - m * s;
    }
    __syncthreads();

    int total8 = M * 16;
    for (int i = blockIdx.x * blockDim.x + threadIdx.x; i < total8; i += gridDim.x * blockDim.x) {
        int c0 = (i & 15) * 8;
        uint4 yv = ((const uint4*)y)[i];
        float2 p0 = __half22float2(*(__half2*)&yv.x);
        float2 p1 = __half22float2(*(__half2*)&yv.y);
        float2 p2 = __half22float2(*(__half2*)&yv.z);
        float2 p3 = __half22float2(*(__half2*)&yv.w);
        float v[8] = {p0.x, p0.y, p1.x, p1.y, p2.x, p2.y, p3.x, p3.y};
#pragma unroll
        for (int q = 0; q < 8; ++q) v[q] = v[q] * sc[c0 + q] + sb[c0 + q];
        if (residual) {
            uint4 rv = ((const uint4*)residual)[i];
            float2 r0 = __half22float2(*(__half2*)&rv.x);
            float2 r1 = __half22float2(*(__half2*)&rv.y);
            float2 r2 = __half22float2(*(__half2*)&rv.z);
            float2 r3 = __half22float2(*(__half2*)&rv.w);
            v[0] += r0.x; v[1] += r0.y; v[2] += r1.x; v[3] += r1.y;
            v[4] += r2.x; v[5] += r2.y; v[6] += r3.x; v[7] += r3.y;
        }
#pragma unroll
        for (int q = 0; q < 8; ++q) v[q] = fmaxf(v[q], 0.f);
        uint4 ov;
        *(__half2*)&ov.x = __floats2half2_rn(v[0], v[1]);
        *(__half2*)&ov.y = __floats2half2_rn(v[2], v[3]);
        *(__half2*)&ov.z = __floats2half2_rn(v[4], v[5]);
        *(__half2*)&ov.w = __floats2half2_rn(v[6], v[7]);
        ((uint4*)out_h16)[i] = ov;
    }
}

// ---------------- head on voxels: dvox = relu(x@w1+b1)@w2 + b2 ----------------
__global__ __launch_bounds__(256)
void head_vox_kernel(const __half* __restrict__ xh,
                     const __half* __restrict__ w1h,
                     const float* __restrict__ b1,
                     const float* __restrict__ w2,
                     const float* __restrict__ b2,
                     float* __restrict__ dvox,
                     int M) {
    extern __shared__ __align__(16) char smem_raw[];
    float* hs = (float*)(smem_raw + 49152);
    __shared__ float b1s[64], b2s[14], w2s[64 * 14];

    const int tid  = threadIdx.x;
    const int warp = tid >> 5, lane = tid & 31;
    const int v0 = blockIdx.x * 128;

    const unsigned sAu = smem_u32(smem_raw);
    const unsigned sBu = sAu + 32768u;

    {
        int row = tid >> 1, c0 = (tid & 1) * 8;
        unsigned ssz = (v0 + row < M) ? 16u : 0u;
        const __half* srcA = xh + (size_t)(v0 + row < M ? v0 + row : 0) * CCH + c0 * 8;
#pragma unroll
        for (int q = 0; q < 8; ++q)
            cp16z(sAu + swz(row, c0 + q), srcA + q * 8, ssz);
    }
    for (int j = tid; j < 1024; j += 256) {
        int row = j >> 3, c = j & 7;
        cp16(sBu + swz64(row, c), w1h + row * 64 + c * 8);
    }
    asm volatile("cp.async.commit_group;\n" ::: "memory");
    if (tid < 64) b1s[tid] = b1[tid];
    if (tid < 14) b2s[tid] = b2[tid];
    for (int j = tid; j < 64 * 14; j += 256) w2s[j] = w2[j];
    asm volatile("cp.async.wait_group 0;\n" ::: "memory");
    __syncthreads();

    float acc[8][4];
#pragma unroll
    for (int ni = 0; ni < 8; ++ni)
#pragma unroll
        for (int q = 0; q < 4; ++q) acc[ni][q] = 0.f;
#pragma unroll
    for (int kc = 0; kc < 8; ++kc) {
        uint32_t a[4];
        ldsm_x4(a, sAu + swz(warp * 16 + (lane & 15), kc * 2 + (lane >> 4)));
#pragma unroll
        for (int nb = 0; nb < 4; ++nb) {
            uint32_t bb[4];
            ldsm_x4_t(bb, sBu + swz64(kc * 16 + (lane & 15), nb * 2 + (lane >> 4)));
            mma_f16(acc[nb * 2 + 0], a, bb[0], bb[1]);
            mma_f16(acc[nb * 2 + 1], a, bb[2], bb[3]);
        }
    }
    {
        int r0 = warp * 16 + (lane >> 2);
        int c0 = (lane & 3) * 2;
#pragma unroll
        for (int ni = 0; ni < 8; ++ni) {
            int c = c0 + ni * 8;
            hs[r0 * 65 + c]           = fmaxf(acc[ni][0] + b1s[c], 0.f);
            hs[r0 * 65 + c + 1]       = fmaxf(acc[ni][1] + b1s[c + 1], 0.f);
            hs[(r0 + 8) * 65 + c]     = fmaxf(acc[ni][2] + b1s[c], 0.f);
            hs[(r0 + 8) * 65 + c + 1] = fmaxf(acc[ni][3] + b1s[c + 1], 0.f);
        }
    }
    __syncthreads();

    {
        int r = tid >> 1;
        int cb = (tid & 1) * 7;
        if (v0 + r < M) {
            float d[7];
#pragma unroll
            for (int c = 0; c < 7; ++c) d[c] = b2s[cb + c];
#pragma unroll 8
            for (int k = 0; k < 64; ++k) {
                float hv = hs[r * 65 + k];
#pragma unroll
                for (int c = 0; c < 7; ++c) d[c] += hv * w2s[k * 14 + cb + c];
            }
            float* dst = dvox + (size_t)(v0 + r) * 14 + cb;
#pragma unroll
            for (int c = 0; c < 7; ++c) dst[c] = d[c];
        }
    }
}

// ---------------- scatter: out = gp + dvox[inv_idx], thread-per-point ---------
__global__ void scatter_out_kernel(const float* __restrict__ gp,
                                   const float* __restrict__ dvox,
                                   const int*   __restrict__ inv_idx,
                                   float* __restrict__ out, int Np) {
    for (int i = blockIdx.x * blockDim.x + threadIdx.x; i < Np; i += gridDim.x * blockDim.x) {
        const float* dr = dvox + (size_t)inv_idx[i] * 14;
        const float* gr = gp + (size_t)i * 14;
        float* orow = out + (size_t)i * 14;
#pragma unroll
        for (int j = 0; j < 14; ++j) orow[j] = gr[j] + dr[j];
    }
}

// ---------------- launch -------------------------------------------------------
extern "C" void kernel_launch(void* const* d_in, const int* in_sizes, int n_in,
                              void* d_out, int out_size) {
    const float* gp       = (const float*)d_in[0];
    const float* w_enc    = (const float*)d_in[1];
    const float* b_enc    = (const float*)d_in[2];
    const float* ln_g     = (const float*)d_in[3];
    const float* ln_b     = (const float*)d_in[4];
    const float* conv_w   = (const float*)d_in[5];
    const float* bn_g     = (const float*)d_in[6];
    const float* bn_b     = (const float*)d_in[7];
    const float* w1       = (const float*)d_in[8];
    const float* b1       = (const float*)d_in[9];
    const float* w2       = (const float*)d_in[10];
    const float* b2       = (const float*)d_in[11];
    const float* nbr_mask = (const float*)d_in[12];
    const int*   inv_idx  = (const int*)d_in[13];
    const int*   nbr_idx  = (const int*)d_in[14];
    float* out = (float*)d_out;

    const int Np = in_sizes[0] / 14;
    const int M  = in_sizes[12] / 27;

    float *px, *pdv, *pcnt, *pstats;
    __half *pyh, *pxh, *pah, *pwh, *pw1h;
    cudaGetSymbolAddress((void**)&px,     g_x);
    cudaGetSymbolAddress((void**)&pdv,    g_dv);
    cudaGetSymbolAddress((void**)&pyh,    g_yh);
    cudaGetSymbolAddress((void**)&pxh,    g_xh);
    cudaGetSymbolAddress((void**)&pah,    g_ah);
    cudaGetSymbolAddress((void**)&pwh,    g_wh);
    cudaGetSymbolAddress((void**)&pw1h,   g_w1h);
    cudaGetSymbolAddress((void**)&pcnt,   g_cnt);
    cudaGetSymbolAddress((void**)&pstats, g_stats);

    const int CONV_SMEM = 2 * ATILE + 2 * BTILE + 27 * BM * 4;  // 224256
    cudaFuncSetAttribute(subm_conv_mma_kernel,
                         cudaFuncAttributeMaxDynamicSharedMemorySize, CONV_SMEM);
    const int HEAD_SMEM = 49152 + 128 * 65 * 4;                 // 82432
    cudaFuncSetAttribute(head_vox_kernel,
                         cudaFuncAttributeMaxDynamicSharedMemorySize, HEAD_SMEM);

    convert_w_kernel<<<1024, 256>>>(conv_w, pwh, 4 * 27 * CCH * CCH);
    convert_w_kernel<<<8, 256>>>(w1, pw1h, CCH * 64);
    cudaMemsetAsync(px, 0, (size_t)M * CCH * sizeof(float));
    cudaMemsetAsync(pcnt, 0, (size_t)M * sizeof(float));
    count_kernel<<<512, 256>>>(inv_idx, pcnt, Np);
    encode_pool_kernel<<<1024, 256>>>(gp, w_enc, b_enc, ln_g, ln_b, inv_idx, pcnt, px, Np);
    pool_div_kernel<<<2048, 256>>>(px, pcnt, pxh, M);

    const int tiles = (M + BM - 1) / BM;
    for (int blk = 0; blk < 2; ++blk) {
        const int l0 = 2 * blk, l1 = 2 * blk + 1;
        // conv1 (fused BN stats, fp16 y) -> BN apply -> ReLU (fp16 out)
        cudaMemsetAsync(pstats, 0, 256 * sizeof(float));
        subm_conv_mma_kernel<<<tiles, 512, CONV_SMEM>>>(
            pxh, pwh + (size_t)l0 * 27 * CCH * CCH, nbr_idx, nbr_mask, pyh, pstats, M);
        bn_apply_kernel<<<2048, 256>>>(pyh, bn_g + l0 * CCH, bn_b + l0 * CCH, pstats,
                                       (const __half*)0, pah, M);
        // conv2 (fused BN stats, fp16 y) -> BN apply + fp16 residual (in-place xh)
        cudaMemsetAsync(pstats, 0, 256 * sizeof(float));
        subm_conv_mma_kernel<<<tiles, 512, CONV_SMEM>>>(
            pah, pwh + (size_t)l1 * 27 * CCH * CCH, nbr_idx, nbr_mask, pyh, pstats, M);
        bn_apply_kernel<<<2048, 256>>>(pyh, bn_g + l1 * CCH, bn_b + l1 * CCH, pstats,
                                       pxh, pxh, M);
    }

    head_vox_kernel<<<(M + 127) / 128, 256, HEAD_SMEM>>>(pxh, pw1h, b1, w2, b2, pdv, M);
    scatter_out_kernel<<<1024, 256>>>(gp, pdv, inv_idx, out, Np);
}